// round 7
// baseline (speedup 1.0000x reference)
#include <cuda_runtime.h>
#include <cuda_bf16.h>
#include <math.h>
#include <stdint.h>

#define LEVELS 4
#define KCB    1024
#define DIM    64
#define NVEC   131072
#define CTAV   128
#define NTHR   256
#define CHUNK  256
#define NCHNK  (KCB / CHUNK)          // 4
#define QELEMS ((size_t)NVEC * DIM)
#define MARGIN 0.5f
#define STRB   144                    // bytes per staged row (conflict-free)
#define BUFB   (CHUNK * STRB)         // 36864

// ---------------- device scratch ----------------
__device__ double        g_mse[LEVELS];
__device__ int           g_counts[LEVELS * KCB];
__device__ float         g_c2[LEVELS * KCB];
__device__ __nv_bfloat16 g_cbh[LEVELS * KCB * DIM];
__device__ int           g_done;

// ---------------- SMEM layout (bytes) ----------------
#define SM_AH     0            // 128 * 144 = 18432
#define SM_B0     18432        // 36864
#define SM_B1     55296        // 36864
#define SM_C2     92160        // 2 bufs * 256 f32 = 2048
#define SM_IDX    94208        // 128 i32
#define SM_IDX2   94720
#define SM_FLG    95232
#define SM_LIST   95744
#define SM_RST    96256        // 64 f32
#define SM_NL     96512
#define SM_REDK   96520
#define SM_LAST   96528
#define SM_WS     96536        // 8 doubles
#define SMEM_TOTAL 96608

// ---------------- helpers ----------------
__device__ __forceinline__ uint32_t smem_u32(const void* p) {
    uint32_t a;
    asm("{ .reg .u64 t; cvta.to.shared.u64 t, %1; cvt.u32.u64 %0, t; }"
        : "=r"(a) : "l"(p));
    return a;
}
__device__ __forceinline__ void ldsm4(uint32_t r[4], uint32_t addr) {
    asm volatile("ldmatrix.sync.aligned.m8n8.x4.shared.b16 {%0,%1,%2,%3}, [%4];"
                 : "=r"(r[0]), "=r"(r[1]), "=r"(r[2]), "=r"(r[3]) : "r"(addr));
}
__device__ __forceinline__ void mma16816(float* d, const uint32_t* a,
                                         uint32_t b0, uint32_t b1) {
    asm volatile(
        "mma.sync.aligned.m16n8k16.row.col.f32.bf16.bf16.f32 "
        "{%0,%1,%2,%3}, {%4,%5,%6,%7}, {%8,%9}, {%0,%1,%2,%3};"
        : "+f"(d[0]), "+f"(d[1]), "+f"(d[2]), "+f"(d[3])
        : "r"(a[0]), "r"(a[1]), "r"(a[2]), "r"(a[3]), "r"(b0), "r"(b1));
}
#define CP16(dst, src) asm volatile("cp.async.cg.shared.global [%0], [%1], 16;" :: "r"(dst), "l"(src))
#define CP_COMMIT()    asm volatile("cp.async.commit_group;" ::: "memory")
#define CP_WAIT0()     asm volatile("cp.async.wait_group 0;" ::: "memory")
#define CP_WAIT1()     asm volatile("cp.async.wait_group 1;" ::: "memory")

__device__ __forceinline__ bool lexless(float v1, int j1, float v2, int j2) {
    return v1 < v2 || (v1 == v2 && j1 < j2);
}
__device__ __forceinline__ void track3(float d, int idx, float& m1, int& i1,
                                       float& m2, int& i2, float& m3) {
    if (d < m1)      { m3 = m2; m2 = m1; i2 = i1; m1 = d; i1 = idx; }
    else if (d < m2) { m3 = m2; m2 = d; i2 = idx; }
    else if (d < m3) { m3 = d; }
}
__device__ __forceinline__ void mergelane(float& m1, int& i1, float& m2,
                                          int& i2, float& m3, int mx) {
    float b1 = __shfl_xor_sync(0xffffffffu, m1, mx);
    int   j1 = __shfl_xor_sync(0xffffffffu, i1, mx);
    float b2 = __shfl_xor_sync(0xffffffffu, m2, mx);
    int   j2 = __shfl_xor_sync(0xffffffffu, i2, mx);
    float b3 = __shfl_xor_sync(0xffffffffu, m3, mx);
    if (lexless(b1, j1, m1, i1)) {
        float t; int ti;
        t = m1; m1 = b1; b1 = t;  ti = i1; i1 = j1; j1 = ti;
        t = m2; m2 = b2; b2 = t;  ti = i2; i2 = j2; j2 = ti;
        t = m3; m3 = b3; b3 = t;
    }
    // a-list best; second = min(a2, b1)
    if (lexless(b1, j1, m2, i2)) { m3 = fminf(m2, b2); m2 = b1; i2 = j1; }
    else                         { m3 = fminf(m3, b1); }
}

// ---------------- prep kernel (zero + c2 + bf16 codebook) ----------------
__global__ void prep_kernel(const float* __restrict__ cb) {
    int t = blockIdx.x * blockDim.x + threadIdx.x;   // 0..4095
    if (t == 0) g_done = 0;
    if (t < LEVELS) g_mse[t] = 0.0;
    if (t < LEVELS * KCB) {
        g_counts[t] = 0;
        const float* v = cb + (size_t)t * DIM;
        __nv_bfloat16* dh = g_cbh + (size_t)t * DIM;
        float s = 0.f;
        #pragma unroll
        for (int d = 0; d < DIM; ++d) {
            float f = v[d];
            s += f * f;
            dh[d] = __float2bfloat16(f);
        }
        g_c2[t] = s;
    }
}

// ---------------- main kernel ----------------
__global__ __launch_bounds__(NTHR, 2)
void rvq_mma_kernel(const float* __restrict__ x,
                    const float* __restrict__ cb,
                    float* __restrict__ out) {
    extern __shared__ char smem[];
    const uint32_t sb = smem_u32(smem);
    const int tid  = threadIdx.x;
    const int lane = tid & 31, warp = tid >> 5;
    const int v = tid >> 1, h = tid & 1;
    const size_t n0 = (size_t)blockIdx.x * CTAV;

    int*   sidx  = (int*)(smem + SM_IDX);
    int*   sidx2 = (int*)(smem + SM_IDX2);
    int*   sflg  = (int*)(smem + SM_FLG);
    int*   list  = (int*)(smem + SM_LIST);
    float* rstage = (float*)(smem + SM_RST);
    int*   nlist = (int*)(smem + SM_NL);
    unsigned long long* redk = (unsigned long long*)(smem + SM_REDK);

    float r[32];
    {
        const float4* xp = (const float4*)(x + (n0 + v) * DIM + h * 32);
        #pragma unroll
        for (int i = 0; i < 8; ++i) {
            float4 t4 = xp[i];
            r[4*i] = t4.x; r[4*i+1] = t4.y; r[4*i+2] = t4.z; r[4*i+3] = t4.w;
        }
    }

    for (int l = 0; l < LEVELS; ++l) {
        // ---- stage A (bf16 hi only) ----
        #pragma unroll
        for (int i = 0; i < 16; ++i) {
            __nv_bfloat16 h0 = __float2bfloat16(r[2*i]);
            __nv_bfloat16 h1 = __float2bfloat16(r[2*i+1]);
            uint32_t wh = (uint32_t)__bfloat16_as_ushort(h0) |
                          ((uint32_t)__bfloat16_as_ushort(h1) << 16);
            *(uint32_t*)(smem + SM_AH + v * STRB + (h * 32 + 2*i) * 2) = wh;
        }
        if (tid == 0) *nlist = 0;

        // ---- prefetch B chunk 0 ----
        {
            const float4* srh = (const float4*)(g_cbh + (size_t)l * KCB * DIM);
            #pragma unroll
            for (int g = tid; g < CHUNK * 8; g += NTHR) {
                int row = g >> 3, col = g & 7;
                CP16(sb + SM_B0 + row * STRB + col * 16, srh + g);
            }
            if (tid < 64)
                CP16(sb + SM_C2 + tid * 16, (const float4*)(g_c2 + l * KCB) + tid);
            CP_COMMIT();
        }
        __syncthreads();

        // ---- A fragments for the level ----
        uint32_t Ah[4][4];
        {
            int rowA = warp * 16 + (lane >> 2);
            int cc   = (lane & 3) * 2;
            #pragma unroll
            for (int ks = 0; ks < 4; ++ks) {
                int kb = ks * 16 + cc;
                int o00 = rowA * STRB + kb * 2;
                int o10 = (rowA + 8) * STRB + kb * 2;
                Ah[ks][0] = *(const uint32_t*)(smem + SM_AH + o00);
                Ah[ks][1] = *(const uint32_t*)(smem + SM_AH + o10);
                Ah[ks][2] = *(const uint32_t*)(smem + SM_AH + o00 + 16);
                Ah[ks][3] = *(const uint32_t*)(smem + SM_AH + o10 + 16);
            }
        }

        float m1a = 3.4e38f, m2a = 3.4e38f, m3a = 3.4e38f;
        float m1b = 3.4e38f, m2b = 3.4e38f, m3b = 3.4e38f;
        int   i1a = 0, i2a = 0, i1b = 0, i2b = 0;

        int buf = 0;
        for (int ci = 0; ci < NCHNK; ++ci) {
            if (ci < NCHNK - 1) {
                const float4* srh = (const float4*)
                    (g_cbh + ((size_t)l * KCB + (ci + 1) * CHUNK) * DIM);
                uint32_t bdst = sb + (buf ? SM_B0 : SM_B1);
                #pragma unroll
                for (int g = tid; g < CHUNK * 8; g += NTHR) {
                    int row = g >> 3, col = g & 7;
                    CP16(bdst + row * STRB + col * 16, srh + g);
                }
                if (tid < 64)
                    CP16(sb + SM_C2 + (buf ^ 1) * 1024 + tid * 16,
                         (const float4*)(g_c2 + l * KCB + (ci + 1) * CHUNK) + tid);
                CP_COMMIT();
                CP_WAIT1();
            } else {
                CP_WAIT0();
            }
            __syncthreads();

            const uint32_t bbase = sb + (buf ? SM_B1 : SM_B0);
            const float* c2s = (const float*)(smem + SM_C2 + buf * 1024);
            const int c0 = ci * CHUNK;

            #pragma unroll 1
            for (int gp = 0; gp < CHUNK / 16; ++gp) {
                float D0[4] = {0.f,0.f,0.f,0.f};
                float D1[4] = {0.f,0.f,0.f,0.f};
                #pragma unroll
                for (int p = 0; p < 2; ++p) {
                    uint32_t bh0[4], bh1[4];
                    uint32_t roff = (uint32_t)((gp * 16 + (lane & 7)) * STRB
                                   + (p * 32 + 8 * (lane >> 3)) * 2);
                    ldsm4(bh0, bbase + roff);
                    ldsm4(bh1, bbase + roff + 8 * STRB);
                    #pragma unroll
                    for (int j = 0; j < 2; ++j) {
                        int ks = 2 * p + j;
                        mma16816(D0, Ah[ks], bh0[2*j], bh0[2*j+1]);
                        mma16816(D1, Ah[ks], bh1[2*j], bh1[2*j+1]);
                    }
                }
                int cc = (lane & 3) * 2;
                int nb = gp * 16 + cc;
                float2 c2v = *(const float2*)(c2s + nb);
                float2 c2w = *(const float2*)(c2s + nb + 8);
                int gi = c0 + nb;
                track3(fmaf(-2.f, D0[0], c2v.x), gi,     m1a,i1a,m2a,i2a,m3a);
                track3(fmaf(-2.f, D0[1], c2v.y), gi + 1, m1a,i1a,m2a,i2a,m3a);
                track3(fmaf(-2.f, D0[2], c2v.x), gi,     m1b,i1b,m2b,i2b,m3b);
                track3(fmaf(-2.f, D0[3], c2v.y), gi + 1, m1b,i1b,m2b,i2b,m3b);
                track3(fmaf(-2.f, D1[0], c2w.x), gi + 8, m1a,i1a,m2a,i2a,m3a);
                track3(fmaf(-2.f, D1[1], c2w.y), gi + 9, m1a,i1a,m2a,i2a,m3a);
                track3(fmaf(-2.f, D1[2], c2w.x), gi + 8, m1b,i1b,m2b,i2b,m3b);
                track3(fmaf(-2.f, D1[3], c2w.y), gi + 9, m1b,i1b,m2b,i2b,m3b);
            }
            __syncthreads();
            buf ^= 1;
        }

        // ---- merge across the 4 lanes of each row quad ----
        mergelane(m1a, i1a, m2a, i2a, m3a, 1);
        mergelane(m1a, i1a, m2a, i2a, m3a, 2);
        mergelane(m1b, i1b, m2b, i2b, m3b, 1);
        mergelane(m1b, i1b, m2b, i2b, m3b, 2);
        if ((lane & 3) == 0) {
            int vA = warp * 16 + (lane >> 2), vB = vA + 8;
            sidx[vA] = i1a; sidx2[vA] = i2a;
            sidx[vB] = i1b; sidx2[vB] = i2b;
            int fA = (m3a - m1a < MARGIN) ? 2 : ((m2a - m1a < MARGIN) ? 1 : 0);
            int fB = (m3b - m1b < MARGIN) ? 2 : ((m2b - m1b < MARGIN) ? 1 : 0);
            sflg[vA] = fA; sflg[vB] = fB;
            if (fA == 2) { int p = atomicAdd(nlist, 1); list[p] = vA; }
            if (fB == 2) { int p = atomicAdd(nlist, 1); list[p] = vB; }
        }
        __syncthreads();

        // ---- full exact rescans (rare) ----
        int nf = *nlist;
        for (int f = 0; f < nf; ++f) {
            int vr = list[f];
            if (tid == 0) *redk = ~0ull;
            if (v == vr) {
                #pragma unroll
                for (int i = 0; i < 8; ++i)
                    *(float4*)(rstage + h * 32 + 4*i) =
                        make_float4(r[4*i], r[4*i+1], r[4*i+2], r[4*i+3]);
            }
            __syncthreads();
            unsigned long long bk = ~0ull;
            #pragma unroll 1
            for (int c = tid; c < KCB; c += NTHR) {
                const float4* cw = (const float4*)(cb + ((size_t)l * KCB + c) * DIM);
                const float4* rp = (const float4*)rstage;
                float s = 0.f;
                #pragma unroll
                for (int i = 0; i < 16; ++i) {
                    float4 a = rp[i], bq = cw[i];
                    s += a.x*bq.x + a.y*bq.y + a.z*bq.z + a.w*bq.w;
                }
                float dist = fmaf(-2.f, s, g_c2[l * KCB + c]);
                uint32_t fb = __float_as_uint(dist);
                fb ^= (fb & 0x80000000u) ? 0xFFFFFFFFu : 0x80000000u;
                unsigned long long key = ((unsigned long long)fb << 32) | (unsigned)c;
                if (key < bk) bk = key;
            }
            atomicMin(redk, bk);
            __syncthreads();
            if (tid == 0) sidx[vr] = (int)(*redk & 0xffffffffu);
            __syncthreads();
        }

        // ---- exact duels (parallel, per-vector owner pair) ----
        int idx = sidx[v];
        int fl  = sflg[v];
        float sA = 0.f, sB = 0.f;
        int iA = idx, iB = sidx2[v];
        if (fl == 1) {
            const float4* ca = (const float4*)(cb + ((size_t)l * KCB + iA) * DIM + h * 32);
            const float4* cbq = (const float4*)(cb + ((size_t)l * KCB + iB) * DIM + h * 32);
            #pragma unroll
            for (int i = 0; i < 8; ++i) {
                float4 a = ca[i], b = cbq[i];
                sA += r[4*i]*a.x + r[4*i+1]*a.y + r[4*i+2]*a.z + r[4*i+3]*a.w;
                sB += r[4*i]*b.x + r[4*i+1]*b.y + r[4*i+2]*b.z + r[4*i+3]*b.w;
            }
        }
        // unconditional shuffles (partner has same fl)
        sA += __shfl_xor_sync(0xffffffffu, sA, 1);
        sB += __shfl_xor_sync(0xffffffffu, sB, 1);
        if (fl == 1) {
            float dA = fmaf(-2.f, sA, g_c2[l * KCB + iA]);
            float dB = fmaf(-2.f, sB, g_c2[l * KCB + iB]);
            idx = lexless(dB, iB, dA, iA) ? iB : iA;
        }

        // ---- commit ----
        {
            const float4* q = (const float4*)(cb + ((size_t)l * KCB + idx) * DIM + h * 32);
            float sse = 0.f;
            #pragma unroll
            for (int i = 0; i < 8; ++i) {
                float4 qv = q[i];
                r[4*i]   -= qv.x; r[4*i+1] -= qv.y;
                r[4*i+2] -= qv.z; r[4*i+3] -= qv.w;
                sse += r[4*i]*r[4*i] + r[4*i+1]*r[4*i+1]
                     + r[4*i+2]*r[4*i+2] + r[4*i+3]*r[4*i+3];
            }
            double ds = (double)sse;
            #pragma unroll
            for (int o = 16; o; o >>= 1) ds += __shfl_down_sync(0xffffffffu, ds, o);
            if (lane == 0) atomicAdd(&g_mse[l], ds);
        }
        if (h == 0) {
            atomicAdd(&g_counts[l * KCB + idx], 1);
            out[QELEMS + (size_t)l * NVEC + n0 + v] = (float)idx;
        }
        __syncthreads();
    }

    // ---- quantized = x - final residual (coalesced via B0 staging) ----
    float* rs = (float*)(smem + SM_B0);
    #pragma unroll
    for (int i = 0; i < 8; ++i)
        *(float4*)(rs + v * 64 + h * 32 + 4*i) =
            make_float4(r[4*i], r[4*i+1], r[4*i+2], r[4*i+3]);
    __syncthreads();
    {
        const float4* xp4 = (const float4*)(x + n0 * DIM);
        const float4* rs4 = (const float4*)rs;
        float4*       op4 = (float4*)(out + n0 * DIM);
        #pragma unroll
        for (int g = tid; g < CTAV * 16; g += NTHR) {
            float4 xv = xp4[g], rv = rs4[g];
            op4[g] = make_float4(xv.x - rv.x, xv.y - rv.y,
                                 xv.z - rv.z, xv.w - rv.w);
        }
    }

    // ---- last CTA runs finalize ----
    int* slast = (int*)(smem + SM_LAST);
    if (tid == 0) {
        __threadfence();
        *slast = (atomicAdd(&g_done, 1) == (int)gridDim.x - 1) ? 1 : 0;
    }
    __syncthreads();
    if (*slast) {
        __threadfence();
        double* ws = (double*)(smem + SM_WS);
        double total = 0.0;
        for (int l = 0; l < LEVELS; ++l) {
            float esum = 0.f;
            for (int i = tid; i < KCB; i += NTHR) {
                float p = (float)g_counts[l * KCB + i] / (float)NVEC;
                esum += -(p * logf(p + 1e-10f));
            }
            double e = (double)esum;
            #pragma unroll
            for (int o = 16; o; o >>= 1) e += __shfl_down_sync(0xffffffffu, e, o);
            if ((tid & 31) == 0) ws[tid >> 5] = e;
            __syncthreads();
            if (tid == 0) {
                double ent = 0.0;
                #pragma unroll
                for (int w = 0; w < 8; ++w) ent += ws[w];
                total += 1.25 * (g_mse[l] / ((double)NVEC * DIM)) + 0.1 * ent;
            }
            __syncthreads();
        }
        if (tid == 0) out[QELEMS + (size_t)LEVELS * NVEC] = (float)total;
    }
}

extern "C" void kernel_launch(void* const* d_in, const int* in_sizes, int n_in,
                              void* d_out, int out_size) {
    const float* x  = (const float*)d_in[0];
    const float* cb = (const float*)d_in[1];
    float* out = (float*)d_out;

    cudaFuncSetAttribute(rvq_mma_kernel,
                         cudaFuncAttributeMaxDynamicSharedMemorySize, SMEM_TOTAL);

    prep_kernel<<<16, 256>>>(cb);
    rvq_mma_kernel<<<NVEC / CTAV, NTHR, SMEM_TOTAL>>>(x, cb, out);
}

// round 9
// speedup vs baseline: 1.1298x; 1.1298x over previous
#include <cuda_runtime.h>
#include <cuda_bf16.h>
#include <math.h>
#include <stdint.h>

#define LEVELS 4
#define KCB    1024
#define DIM    64
#define NVEC   131072
#define CTAV   128
#define NTHR   256
#define CHUNK  128
#define NCHNK  (KCB / CHUNK)          // 8
#define QELEMS ((size_t)NVEC * DIM)
#define MARGIN 0.6f
#define STRB   144                    // bytes per staged row (conflict-free)

// ---------------- device scratch ----------------
__device__ double        g_mse[LEVELS];
__device__ int           g_counts[LEVELS * KCB];
__device__ float         g_c2[LEVELS * KCB];
__device__ __nv_bfloat16 g_cbh[LEVELS * KCB * DIM];
__device__ int           g_done;

// ---------------- SMEM layout (bytes) ----------------
#define SM_AH     0            // 128 * 144 = 18432
#define SM_B0     18432        // 18432
#define SM_B1     36864        // 18432
#define SM_C2     55296        // 2 bufs * 128 f32 = 1024
#define SM_IDX    56320        // 128 i32
#define SM_IDX2   56832
#define SM_FLG    57344
#define SM_LIST   57856
#define SM_RST    58368        // 64 f32
#define SM_NL     58624
#define SM_REDK   58632
#define SM_LAST   58640
#define SM_WS     58648        // 8 doubles
#define SMEM_TOTAL 58752

// ---------------- helpers ----------------
__device__ __forceinline__ uint32_t smem_u32(const void* p) {
    uint32_t a;
    asm("{ .reg .u64 t; cvta.to.shared.u64 t, %1; cvt.u32.u64 %0, t; }"
        : "=r"(a) : "l"(p));
    return a;
}
__device__ __forceinline__ void ldsm4(uint32_t r[4], uint32_t addr) {
    asm volatile("ldmatrix.sync.aligned.m8n8.x4.shared.b16 {%0,%1,%2,%3}, [%4];"
                 : "=r"(r[0]), "=r"(r[1]), "=r"(r[2]), "=r"(r[3]) : "r"(addr));
}
__device__ __forceinline__ void mma16816(float* d, const uint32_t* a,
                                         uint32_t b0, uint32_t b1) {
    asm volatile(
        "mma.sync.aligned.m16n8k16.row.col.f32.bf16.bf16.f32 "
        "{%0,%1,%2,%3}, {%4,%5,%6,%7}, {%8,%9}, {%0,%1,%2,%3};"
        : "+f"(d[0]), "+f"(d[1]), "+f"(d[2]), "+f"(d[3])
        : "r"(a[0]), "r"(a[1]), "r"(a[2]), "r"(a[3]), "r"(b0), "r"(b1));
}
#define CP16(dst, src) asm volatile("cp.async.cg.shared.global [%0], [%1], 16;" :: "r"(dst), "l"(src))
#define CP_COMMIT()    asm volatile("cp.async.commit_group;" ::: "memory")
#define CP_WAIT0()     asm volatile("cp.async.wait_group 0;" ::: "memory")
#define CP_WAIT1()     asm volatile("cp.async.wait_group 1;" ::: "memory")

// sortable key: monotone f32 map, low 10 bits replaced by codeword index
__device__ __forceinline__ uint32_t dkey(float d, uint32_t idx) {
    uint32_t fb = __float_as_uint(d);
    fb ^= (uint32_t)((int32_t)fb >> 31) | 0x80000000u;
    return (fb & 0xFFFFFC00u) | idx;
}
__device__ __forceinline__ float unkey(uint32_t k) {
    uint32_t u = k & 0xFFFFFC00u;
    uint32_t fb = (u & 0x80000000u) ? (u ^ 0x80000000u) : (~u & 0xFFFFFC00u);
    return __uint_as_float(fb);
}
// insert one key into sorted (K1<=K2<=K3)
__device__ __forceinline__ void ins3(uint32_t& K1, uint32_t& K2, uint32_t& K3,
                                     uint32_t g) {
    uint32_t b = umax(K1, g); K1 = umin(K1, g);
    uint32_t d = umax(K2, b); K2 = umin(K2, b);
    K3 = umin(K3, d);
}
// insert key known >= some already-inserted key (starts at K2)
__device__ __forceinline__ void ins2(uint32_t& K2, uint32_t& K3, uint32_t g) {
    uint32_t f = umax(K2, g); K2 = umin(K2, g);
    K3 = umin(K3, f);
}
// fold 4 dists into running top-3 keys
__device__ __forceinline__ void fold4(uint32_t& K1, uint32_t& K2, uint32_t& K3,
                                      float d0, float d1, float d8, float d9,
                                      uint32_t gi) {
    uint32_t k0 = dkey(d0, gi),     k1 = dkey(d1, gi + 1);
    uint32_t k8 = dkey(d8, gi + 8), k9 = dkey(d9, gi + 9);
    uint32_t lo01 = umin(k0, k1), hi01 = umax(k0, k1);
    uint32_t lo89 = umin(k8, k9), hi89 = umax(k8, k9);
    uint32_t g1 = umin(lo01, lo89);
    uint32_t g2 = umin(umax(lo01, lo89), umin(hi01, hi89));
    ins3(K1, K2, K3, g1);
    ins2(K2, K3, g2);
}
__device__ __forceinline__ void lanemerge(uint32_t& K1, uint32_t& K2,
                                          uint32_t& K3, int mx) {
    uint32_t o1 = __shfl_xor_sync(0xffffffffu, K1, mx);
    uint32_t o2 = __shfl_xor_sync(0xffffffffu, K2, mx);
    uint32_t o3 = __shfl_xor_sync(0xffffffffu, K3, mx);
    ins3(K1, K2, K3, o1);
    ins2(K2, K3, o2);
    K3 = umin(K3, o3);
}
__device__ __forceinline__ bool lexless(float v1, int j1, float v2, int j2) {
    return v1 < v2 || (v1 == v2 && j1 < j2);
}

// ---------------- prep kernel ----------------
__global__ void prep_kernel(const float* __restrict__ cb) {
    int t = blockIdx.x * blockDim.x + threadIdx.x;
    if (t == 0) g_done = 0;
    if (t < LEVELS) g_mse[t] = 0.0;
    if (t < LEVELS * KCB) {
        g_counts[t] = 0;
        const float* v = cb + (size_t)t * DIM;
        __nv_bfloat16* dh = g_cbh + (size_t)t * DIM;
        float s = 0.f;
        #pragma unroll
        for (int d = 0; d < DIM; ++d) {
            float f = v[d];
            s += f * f;
            dh[d] = __float2bfloat16(f);
        }
        g_c2[t] = s;
    }
}

// ---------------- main kernel ----------------
__global__ __launch_bounds__(NTHR, 3)
void rvq_mma_kernel(const float* __restrict__ x,
                    const float* __restrict__ cb,
                    float* __restrict__ out) {
    extern __shared__ char smem[];
    const uint32_t sb = smem_u32(smem);
    const int tid  = threadIdx.x;
    const int lane = tid & 31, warp = tid >> 5;
    const int v = tid >> 1, h = tid & 1;
    const size_t n0 = (size_t)blockIdx.x * CTAV;

    int*   sidx  = (int*)(smem + SM_IDX);
    int*   sidx2 = (int*)(smem + SM_IDX2);
    int*   sflg  = (int*)(smem + SM_FLG);
    int*   list  = (int*)(smem + SM_LIST);
    float* rstage = (float*)(smem + SM_RST);
    int*   nlist = (int*)(smem + SM_NL);
    unsigned long long* redk = (unsigned long long*)(smem + SM_REDK);

    float r[32];
    {
        const float4* xp = (const float4*)(x + (n0 + v) * DIM + h * 32);
        #pragma unroll
        for (int i = 0; i < 8; ++i) {
            float4 t4 = xp[i];
            r[4*i] = t4.x; r[4*i+1] = t4.y; r[4*i+2] = t4.z; r[4*i+3] = t4.w;
        }
    }

    for (int l = 0; l < LEVELS; ++l) {
        // ---- stage A (bf16) ----
        #pragma unroll
        for (int i = 0; i < 16; ++i) {
            __nv_bfloat16 h0 = __float2bfloat16(r[2*i]);
            __nv_bfloat16 h1 = __float2bfloat16(r[2*i+1]);
            uint32_t wh = (uint32_t)__bfloat16_as_ushort(h0) |
                          ((uint32_t)__bfloat16_as_ushort(h1) << 16);
            *(uint32_t*)(smem + SM_AH + v * STRB + (h * 32 + 2*i) * 2) = wh;
        }
        if (tid == 0) *nlist = 0;

        // ---- prefetch B chunk 0 ----
        {
            const float4* srh = (const float4*)(g_cbh + (size_t)l * KCB * DIM);
            #pragma unroll
            for (int g = tid; g < CHUNK * 8; g += NTHR) {
                int row = g >> 3, col = g & 7;
                CP16(sb + SM_B0 + row * STRB + col * 16, srh + g);
            }
            if (tid < 32)
                CP16(sb + SM_C2 + tid * 16, (const float4*)(g_c2 + l * KCB) + tid);
            CP_COMMIT();
        }
        __syncthreads();

        // ---- A fragments for the level ----
        uint32_t Ah[4][4];
        {
            int rowA = warp * 16 + (lane >> 2);
            int cc   = (lane & 3) * 2;
            #pragma unroll
            for (int ks = 0; ks < 4; ++ks) {
                int kb = ks * 16 + cc;
                int o00 = rowA * STRB + kb * 2;
                int o10 = (rowA + 8) * STRB + kb * 2;
                Ah[ks][0] = *(const uint32_t*)(smem + SM_AH + o00);
                Ah[ks][1] = *(const uint32_t*)(smem + SM_AH + o10);
                Ah[ks][2] = *(const uint32_t*)(smem + SM_AH + o00 + 16);
                Ah[ks][3] = *(const uint32_t*)(smem + SM_AH + o10 + 16);
            }
        }

        uint32_t Ka1 = 0xFFFFFFFFu, Ka2 = 0xFFFFFFFFu, Ka3 = 0xFFFFFFFFu;
        uint32_t Kb1 = 0xFFFFFFFFu, Kb2 = 0xFFFFFFFFu, Kb3 = 0xFFFFFFFFu;

        int buf = 0;
        for (int ci = 0; ci < NCHNK; ++ci) {
            if (ci < NCHNK - 1) {
                const float4* srh = (const float4*)
                    (g_cbh + ((size_t)l * KCB + (ci + 1) * CHUNK) * DIM);
                uint32_t bdst = sb + (buf ? SM_B0 : SM_B1);
                #pragma unroll
                for (int g = tid; g < CHUNK * 8; g += NTHR) {
                    int row = g >> 3, col = g & 7;
                    CP16(bdst + row * STRB + col * 16, srh + g);
                }
                if (tid < 32)
                    CP16(sb + SM_C2 + (buf ^ 1) * 512 + tid * 16,
                         (const float4*)(g_c2 + l * KCB + (ci + 1) * CHUNK) + tid);
                CP_COMMIT();
                CP_WAIT1();
            } else {
                CP_WAIT0();
            }
            __syncthreads();

            const uint32_t bbase = sb + (buf ? SM_B1 : SM_B0);
            const float* c2s = (const float*)(smem + SM_C2 + buf * 512);
            const int c0 = ci * CHUNK;

            #pragma unroll 1
            for (int gp = 0; gp < CHUNK / 16; ++gp) {
                float D0[4] = {0.f,0.f,0.f,0.f};
                float D1[4] = {0.f,0.f,0.f,0.f};
                #pragma unroll
                for (int p = 0; p < 2; ++p) {
                    uint32_t bh0[4], bh1[4];
                    uint32_t roff = (uint32_t)((gp * 16 + (lane & 7)) * STRB
                                   + (p * 32 + 8 * (lane >> 3)) * 2);
                    ldsm4(bh0, bbase + roff);
                    ldsm4(bh1, bbase + roff + 8 * STRB);
                    #pragma unroll
                    for (int j = 0; j < 2; ++j) {
                        int ks = 2 * p + j;
                        mma16816(D0, Ah[ks], bh0[2*j], bh0[2*j+1]);
                        mma16816(D1, Ah[ks], bh1[2*j], bh1[2*j+1]);
                    }
                }
                int cc = (lane & 3) * 2;
                int nb = gp * 16 + cc;
                float2 c2v = *(const float2*)(c2s + nb);
                float2 c2w = *(const float2*)(c2s + nb + 8);
                uint32_t gi = (uint32_t)(c0 + nb);
                fold4(Ka1, Ka2, Ka3,
                      fmaf(-2.f, D0[0], c2v.x), fmaf(-2.f, D0[1], c2v.y),
                      fmaf(-2.f, D1[0], c2w.x), fmaf(-2.f, D1[1], c2w.y), gi);
                fold4(Kb1, Kb2, Kb3,
                      fmaf(-2.f, D0[2], c2v.x), fmaf(-2.f, D0[3], c2v.y),
                      fmaf(-2.f, D1[2], c2w.x), fmaf(-2.f, D1[3], c2w.y), gi);
            }
            __syncthreads();
            buf ^= 1;
        }

        // ---- merge across the 4 lanes of each row quad (key space) ----
        lanemerge(Ka1, Ka2, Ka3, 1);
        lanemerge(Ka1, Ka2, Ka3, 2);
        lanemerge(Kb1, Kb2, Kb3, 1);
        lanemerge(Kb1, Kb2, Kb3, 2);
        if ((lane & 3) == 0) {
            int vA = warp * 16 + (lane >> 2), vB = vA + 8;
            float m1a = unkey(Ka1), m2a = unkey(Ka2), m3a = unkey(Ka3);
            float m1b = unkey(Kb1), m2b = unkey(Kb2), m3b = unkey(Kb3);
            sidx[vA] = (int)(Ka1 & 1023u); sidx2[vA] = (int)(Ka2 & 1023u);
            sidx[vB] = (int)(Kb1 & 1023u); sidx2[vB] = (int)(Kb2 & 1023u);
            int fA = (m3a - m1a < MARGIN) ? 2 : ((m2a - m1a < MARGIN) ? 1 : 0);
            int fB = (m3b - m1b < MARGIN) ? 2 : ((m2b - m1b < MARGIN) ? 1 : 0);
            sflg[vA] = fA; sflg[vB] = fB;
            if (fA == 2) { int p = atomicAdd(nlist, 1); list[p] = vA; }
            if (fB == 2) { int p = atomicAdd(nlist, 1); list[p] = vB; }
        }
        __syncthreads();

        // ---- full exact rescans (rare) ----
        int nf = *nlist;
        for (int f = 0; f < nf; ++f) {
            int vr = list[f];
            if (tid == 0) *redk = ~0ull;
            if (v == vr) {
                #pragma unroll
                for (int i = 0; i < 8; ++i)
                    *(float4*)(rstage + h * 32 + 4*i) =
                        make_float4(r[4*i], r[4*i+1], r[4*i+2], r[4*i+3]);
            }
            __syncthreads();
            unsigned long long bk = ~0ull;
            #pragma unroll 1
            for (int c = tid; c < KCB; c += NTHR) {
                const float4* cw = (const float4*)(cb + ((size_t)l * KCB + c) * DIM);
                const float4* rp = (const float4*)rstage;
                float s = 0.f;
                #pragma unroll
                for (int i = 0; i < 16; ++i) {
                    float4 a = rp[i], bq = cw[i];
                    s += a.x*bq.x + a.y*bq.y + a.z*bq.z + a.w*bq.w;
                }
                float dist = fmaf(-2.f, s, g_c2[l * KCB + c]);
                uint32_t fb = __float_as_uint(dist);
                fb ^= (fb & 0x80000000u) ? 0xFFFFFFFFu : 0x80000000u;
                unsigned long long key = ((unsigned long long)fb << 32) | (unsigned)c;
                if (key < bk) bk = key;
            }
            atomicMin(redk, bk);
            __syncthreads();
            if (tid == 0) sidx[vr] = (int)(*redk & 0xffffffffu);
            __syncthreads();
        }

        // ---- exact duels (parallel, per-vector owner pair) ----
        int idx = sidx[v];
        int fl  = sflg[v];
        float sA = 0.f, sB = 0.f;
        int iA = idx, iB = sidx2[v];
        if (fl == 1) {
            const float4* ca = (const float4*)(cb + ((size_t)l * KCB + iA) * DIM + h * 32);
            const float4* cbq = (const float4*)(cb + ((size_t)l * KCB + iB) * DIM + h * 32);
            #pragma unroll
            for (int i = 0; i < 8; ++i) {
                float4 a = ca[i], b = cbq[i];
                sA += r[4*i]*a.x + r[4*i+1]*a.y + r[4*i+2]*a.z + r[4*i+3]*a.w;
                sB += r[4*i]*b.x + r[4*i+1]*b.y + r[4*i+2]*b.z + r[4*i+3]*b.w;
            }
        }
        sA += __shfl_xor_sync(0xffffffffu, sA, 1);
        sB += __shfl_xor_sync(0xffffffffu, sB, 1);
        if (fl == 1) {
            float dA = fmaf(-2.f, sA, g_c2[l * KCB + iA]);
            float dB = fmaf(-2.f, sB, g_c2[l * KCB + iB]);
            idx = lexless(dB, iB, dA, iA) ? iB : iA;
        }

        // ---- commit ----
        {
            const float4* q = (const float4*)(cb + ((size_t)l * KCB + idx) * DIM + h * 32);
            float sse = 0.f;
            #pragma unroll
            for (int i = 0; i < 8; ++i) {
                float4 qv = q[i];
                r[4*i]   -= qv.x; r[4*i+1] -= qv.y;
                r[4*i+2] -= qv.z; r[4*i+3] -= qv.w;
                sse += r[4*i]*r[4*i] + r[4*i+1]*r[4*i+1]
                     + r[4*i+2]*r[4*i+2] + r[4*i+3]*r[4*i+3];
            }
            double ds = (double)sse;
            #pragma unroll
            for (int o = 16; o; o >>= 1) ds += __shfl_down_sync(0xffffffffu, ds, o);
            if (lane == 0) atomicAdd(&g_mse[l], ds);
        }
        if (h == 0) {
            atomicAdd(&g_counts[l * KCB + idx], 1);
            out[QELEMS + (size_t)l * NVEC + n0 + v] = (float)idx;
        }
        __syncthreads();
    }

    // ---- quantized = x - final residual (coalesced via B0/B1 staging) ----
    float* rs = (float*)(smem + SM_B0);     // 36.8KB region, reused
    #pragma unroll
    for (int i = 0; i < 8; ++i)
        *(float4*)(rs + v * 64 + h * 32 + 4*i) =
            make_float4(r[4*i], r[4*i+1], r[4*i+2], r[4*i+3]);
    __syncthreads();
    {
        const float4* xp4 = (const float4*)(x + n0 * DIM);
        const float4* rs4 = (const float4*)rs;
        float4*       op4 = (float4*)(out + n0 * DIM);
        #pragma unroll
        for (int g = tid; g < CTAV * 16; g += NTHR) {
            float4 xv = xp4[g], rv = rs4[g];
            op4[g] = make_float4(xv.x - rv.x, xv.y - rv.y,
                                 xv.z - rv.z, xv.w - rv.w);
        }
    }

    // ---- last CTA runs finalize ----
    int* slast = (int*)(smem + SM_LAST);
    if (tid == 0) {
        __threadfence();
        *slast = (atomicAdd(&g_done, 1) == (int)gridDim.x - 1) ? 1 : 0;
    }
    __syncthreads();
    if (*slast) {
        __threadfence();
        double* ws = (double*)(smem + SM_WS);
        double total = 0.0;
        for (int l = 0; l < LEVELS; ++l) {
            float esum = 0.f;
            for (int i = tid; i < KCB; i += NTHR) {
                float p = (float)g_counts[l * KCB + i] / (float)NVEC;
                esum += -(p * logf(p + 1e-10f));
            }
            double e = (double)esum;
            #pragma unroll
            for (int o = 16; o; o >>= 1) e += __shfl_down_sync(0xffffffffu, e, o);
            if ((tid & 31) == 0) ws[tid >> 5] = e;
            __syncthreads();
            if (tid == 0) {
                double ent = 0.0;
                #pragma unroll
                for (int w = 0; w < 8; ++w) ent += ws[w];
                total += 1.25 * (g_mse[l] / ((double)NVEC * DIM)) + 0.1 * ent;
            }
            __syncthreads();
        }
        if (tid == 0) out[QELEMS + (size_t)LEVELS * NVEC] = (float)total;
    }
}

extern "C" void kernel_launch(void* const* d_in, const int* in_sizes, int n_in,
                              void* d_out, int out_size) {
    const float* x  = (const float*)d_in[0];
    const float* cb = (const float*)d_in[1];
    float* out = (float*)d_out;

    cudaFuncSetAttribute(rvq_mma_kernel,
                         cudaFuncAttributeMaxDynamicSharedMemorySize, SMEM_TOTAL);

    prep_kernel<<<16, 256>>>(cb);
    rvq_mma_kernel<<<NVEC / CTAV, NTHR, SMEM_TOTAL>>>(x, cb, out);
}

// round 10
// speedup vs baseline: 1.1484x; 1.0165x over previous
#include <cuda_runtime.h>
#include <cuda_bf16.h>
#include <math.h>
#include <stdint.h>

#define LEVELS 4
#define KCB    1024
#define DIM    64
#define NVEC   131072
#define CTAV   128
#define NTHR   256
#define CHUNK  128
#define NCHNK  (KCB / CHUNK)          // 8
#define QELEMS ((size_t)NVEC * DIM)
#define MARGIN 0.6f
#define STRB   144                    // bytes per staged row (conflict-free)

// ---------------- device scratch ----------------
__device__ double        g_mse[LEVELS];
__device__ int           g_counts[LEVELS * KCB];
__device__ float         g_c2[LEVELS * KCB];
__device__ __nv_bfloat16 g_cbh[LEVELS * KCB * DIM];
__device__ int           g_done;

// ---------------- SMEM layout (bytes) ----------------
#define SM_AH     0            // 128 * 144 = 18432
#define SM_B0     18432        // 18432
#define SM_B1     36864        // 18432
#define SM_C2     55296        // 2 bufs * 128 f32 = 1024
#define SM_IDX    56320        // 128 i32
#define SM_IDX2   56832
#define SM_FLG    57344
#define SM_LIST   57856
#define SM_RST    58368        // 64 f32
#define SM_NL     58624
#define SM_REDK   58632
#define SM_LAST   58640
#define SM_WS     58648        // 8 doubles
#define SMEM_TOTAL 58752

// ---------------- helpers ----------------
__device__ __forceinline__ uint32_t smem_u32(const void* p) {
    uint32_t a;
    asm("{ .reg .u64 t; cvta.to.shared.u64 t, %1; cvt.u32.u64 %0, t; }"
        : "=r"(a) : "l"(p));
    return a;
}
__device__ __forceinline__ void ldsm4(uint32_t r[4], uint32_t addr) {
    asm volatile("ldmatrix.sync.aligned.m8n8.x4.shared.b16 {%0,%1,%2,%3}, [%4];"
                 : "=r"(r[0]), "=r"(r[1]), "=r"(r[2]), "=r"(r[3]) : "r"(addr));
}
__device__ __forceinline__ void mma16816(float* d, const uint32_t* a,
                                         uint32_t b0, uint32_t b1) {
    asm volatile(
        "mma.sync.aligned.m16n8k16.row.col.f32.bf16.bf16.f32 "
        "{%0,%1,%2,%3}, {%4,%5,%6,%7}, {%8,%9}, {%0,%1,%2,%3};"
        : "+f"(d[0]), "+f"(d[1]), "+f"(d[2]), "+f"(d[3])
        : "r"(a[0]), "r"(a[1]), "r"(a[2]), "r"(a[3]), "r"(b0), "r"(b1));
}
#define CP16(dst, src) asm volatile("cp.async.cg.shared.global [%0], [%1], 16;" :: "r"(dst), "l"(src))
#define CP_COMMIT()    asm volatile("cp.async.commit_group;" ::: "memory")
#define CP_WAIT0()     asm volatile("cp.async.wait_group 0;" ::: "memory")
#define CP_WAIT1()     asm volatile("cp.async.wait_group 1;" ::: "memory")

// sortable key: monotone f32 map, low 10 bits replaced by codeword index
__device__ __forceinline__ uint32_t dkey(float d, uint32_t idx) {
    uint32_t fb = __float_as_uint(d);
    fb ^= (uint32_t)((int32_t)fb >> 31) | 0x80000000u;
    return (fb & 0xFFFFFC00u) | (idx & 1023u);
}
__device__ __forceinline__ float unkey(uint32_t k) {
    uint32_t u = k & 0xFFFFFC00u;
    uint32_t fb = (u & 0x80000000u) ? (u ^ 0x80000000u) : (~u & 0xFFFFFC00u);
    return __uint_as_float(fb);
}
// insert one key into sorted (K1<=K2<=K3)
__device__ __forceinline__ void ins3(uint32_t& K1, uint32_t& K2, uint32_t& K3,
                                     uint32_t g) {
    uint32_t b = umax(K1, g); K1 = umin(K1, g);
    uint32_t d = umax(K2, b); K2 = umin(K2, b);
    K3 = umin(K3, d);
}
// insert key known >= some already-inserted key
__device__ __forceinline__ void ins2(uint32_t& K2, uint32_t& K3, uint32_t g) {
    uint32_t f = umax(K2, g); K2 = umin(K2, g);
    K3 = umin(K3, f);
}
// fold 4 dists into running top-3 keys (true 3-of-4 extraction)
__device__ __forceinline__ void fold4(uint32_t& K1, uint32_t& K2, uint32_t& K3,
                                      float d0, float d1, float d8, float d9,
                                      uint32_t gi) {
    uint32_t k0 = dkey(d0, gi),     k1 = dkey(d1, gi + 1);
    uint32_t k8 = dkey(d8, gi + 8), k9 = dkey(d9, gi + 9);
    uint32_t lo1 = umin(k0, k1), hi1 = umax(k0, k1);
    uint32_t lo2 = umin(k8, k9), hi2 = umax(k8, k9);
    uint32_t g1 = umin(lo1, lo2);
    uint32_t m  = umax(lo1, lo2), n = umin(hi1, hi2);
    uint32_t g2 = umin(m, n);
    uint32_t g3 = umin(umax(m, n), umax(hi1, hi2));
    ins3(K1, K2, K3, g1);
    ins2(K2, K3, g2);
    K3 = umin(K3, g3);
}
__device__ __forceinline__ void lanemerge(uint32_t& K1, uint32_t& K2,
                                          uint32_t& K3, int mx) {
    uint32_t o1 = __shfl_xor_sync(0xffffffffu, K1, mx);
    uint32_t o2 = __shfl_xor_sync(0xffffffffu, K2, mx);
    uint32_t o3 = __shfl_xor_sync(0xffffffffu, K3, mx);
    ins3(K1, K2, K3, o1);
    ins2(K2, K3, o2);
    K3 = umin(K3, o3);
}
__device__ __forceinline__ bool lexless(float v1, int j1, float v2, int j2) {
    return v1 < v2 || (v1 == v2 && j1 < j2);
}

// ---------------- prep kernel ----------------
__global__ void prep_kernel(const float* __restrict__ cb) {
    int t = blockIdx.x * blockDim.x + threadIdx.x;
    if (t == 0) g_done = 0;
    if (t < LEVELS) g_mse[t] = 0.0;
    if (t < LEVELS * KCB) {
        g_counts[t] = 0;
        const float* v = cb + (size_t)t * DIM;
        __nv_bfloat16* dh = g_cbh + (size_t)t * DIM;
        float s = 0.f;
        #pragma unroll
        for (int d = 0; d < DIM; ++d) {
            float f = v[d];
            s += f * f;
            dh[d] = __float2bfloat16(f);
        }
        g_c2[t] = s;
    }
}

// ---------------- main kernel ----------------
__global__ __launch_bounds__(NTHR, 3)
void rvq_mma_kernel(const float* __restrict__ x,
                    const float* __restrict__ cb,
                    float* __restrict__ out) {
    extern __shared__ char smem[];
    const uint32_t sb = smem_u32(smem);
    const int tid  = threadIdx.x;
    const int lane = tid & 31, warp = tid >> 5;
    const int v = tid >> 1, h = tid & 1;
    const size_t n0 = (size_t)blockIdx.x * CTAV;

    int*   sidx  = (int*)(smem + SM_IDX);
    int*   sidx2 = (int*)(smem + SM_IDX2);
    int*   sflg  = (int*)(smem + SM_FLG);
    int*   list  = (int*)(smem + SM_LIST);
    float* rstage = (float*)(smem + SM_RST);
    int*   nlist = (int*)(smem + SM_NL);
    unsigned long long* redk = (unsigned long long*)(smem + SM_REDK);

    float r[32];
    {
        const float4* xp = (const float4*)(x + (n0 + v) * DIM + h * 32);
        #pragma unroll
        for (int i = 0; i < 8; ++i) {
            float4 t4 = xp[i];
            r[4*i] = t4.x; r[4*i+1] = t4.y; r[4*i+2] = t4.z; r[4*i+3] = t4.w;
        }
    }

    for (int l = 0; l < LEVELS; ++l) {
        // ---- stage A (bf16) ----
        #pragma unroll
        for (int i = 0; i < 16; ++i) {
            __nv_bfloat16 h0 = __float2bfloat16(r[2*i]);
            __nv_bfloat16 h1 = __float2bfloat16(r[2*i+1]);
            uint32_t wh = (uint32_t)__bfloat16_as_ushort(h0) |
                          ((uint32_t)__bfloat16_as_ushort(h1) << 16);
            *(uint32_t*)(smem + SM_AH + v * STRB + (h * 32 + 2*i) * 2) = wh;
        }
        if (tid == 0) *nlist = 0;

        // ---- prefetch B chunk 0 ----
        {
            const float4* srh = (const float4*)(g_cbh + (size_t)l * KCB * DIM);
            #pragma unroll
            for (int g = tid; g < CHUNK * 8; g += NTHR) {
                int row = g >> 3, col = g & 7;
                CP16(sb + SM_B0 + row * STRB + col * 16, srh + g);
            }
            if (tid < 32)
                CP16(sb + SM_C2 + tid * 16, (const float4*)(g_c2 + l * KCB) + tid);
            CP_COMMIT();
        }
        __syncthreads();

        // ---- A fragments for the level ----
        uint32_t Ah[4][4];
        {
            int rowA = warp * 16 + (lane >> 2);
            int cc   = (lane & 3) * 2;
            #pragma unroll
            for (int ks = 0; ks < 4; ++ks) {
                int kb = ks * 16 + cc;
                int o00 = rowA * STRB + kb * 2;
                int o10 = (rowA + 8) * STRB + kb * 2;
                Ah[ks][0] = *(const uint32_t*)(smem + SM_AH + o00);
                Ah[ks][1] = *(const uint32_t*)(smem + SM_AH + o10);
                Ah[ks][2] = *(const uint32_t*)(smem + SM_AH + o00 + 16);
                Ah[ks][3] = *(const uint32_t*)(smem + SM_AH + o10 + 16);
            }
        }

        uint32_t Ka1 = 0xFFFFFFFFu, Ka2 = 0xFFFFFFFFu, Ka3 = 0xFFFFFFFFu;
        uint32_t Kb1 = 0xFFFFFFFFu, Kb2 = 0xFFFFFFFFu, Kb3 = 0xFFFFFFFFu;

        // pipelined D / c2 (parity-double-buffered registers).
        // fake previous gp: D = -3.4e38 -> dist = +huge -> keys never win.
        float D[2][8];
        float c2q[2][4];
        #pragma unroll
        for (int q = 0; q < 8; ++q) D[1][q] = -3.4e38f;
        #pragma unroll
        for (int q = 0; q < 4; ++q) c2q[1][q] = 0.f;

        int buf = 0;
        for (int ci = 0; ci < NCHNK; ++ci) {
            if (ci < NCHNK - 1) {
                const float4* srh = (const float4*)
                    (g_cbh + ((size_t)l * KCB + (ci + 1) * CHUNK) * DIM);
                uint32_t bdst = sb + (buf ? SM_B0 : SM_B1);
                #pragma unroll
                for (int g = tid; g < CHUNK * 8; g += NTHR) {
                    int row = g >> 3, col = g & 7;
                    CP16(bdst + row * STRB + col * 16, srh + g);
                }
                if (tid < 32)
                    CP16(sb + SM_C2 + (buf ^ 1) * 512 + tid * 16,
                         (const float4*)(g_c2 + l * KCB + (ci + 1) * CHUNK) + tid);
                CP_COMMIT();
                CP_WAIT1();
            } else {
                CP_WAIT0();
            }
            __syncthreads();

            const uint32_t bbase = sb + (buf ? SM_B1 : SM_B0);
            const float* c2s = (const float*)(smem + SM_C2 + buf * 512);
            const int c0 = ci * CHUNK;

            #pragma unroll 2
            for (int gp = 0; gp < 8; ++gp) {
                const int cur = gp & 1, prv = cur ^ 1;
                // (1) issue all LDSMs for this gp (no dependencies)
                uint32_t bf[16];
                uint32_t roff = (uint32_t)((gp * 16 + (lane & 7)) * STRB
                               + (8 * (lane >> 3)) * 2);
                ldsm4(bf,      bbase + roff);
                ldsm4(bf + 4,  bbase + roff + 8 * STRB);
                ldsm4(bf + 8,  bbase + roff + 64);
                ldsm4(bf + 12, bbase + roff + 64 + 8 * STRB);
                // (2) c2 for this gp (consumed next iteration)
                int nb = gp * 16 + (lane & 3) * 2;
                float2 a2 = *(const float2*)(c2s + nb);
                float2 b2 = *(const float2*)(c2s + nb + 8);
                c2q[cur][0] = a2.x; c2q[cur][1] = a2.y;
                c2q[cur][2] = b2.x; c2q[cur][3] = b2.y;
                // (3) fold PREVIOUS gp's distances — covers LDSM latency
                {
                    uint32_t gi = (uint32_t)(c0 + gp * 16 - 16 + (lane & 3) * 2);
                    fold4(Ka1, Ka2, Ka3,
                          fmaf(-2.f, D[prv][0], c2q[prv][0]),
                          fmaf(-2.f, D[prv][1], c2q[prv][1]),
                          fmaf(-2.f, D[prv][4], c2q[prv][2]),
                          fmaf(-2.f, D[prv][5], c2q[prv][3]), gi);
                    fold4(Kb1, Kb2, Kb3,
                          fmaf(-2.f, D[prv][2], c2q[prv][0]),
                          fmaf(-2.f, D[prv][3], c2q[prv][1]),
                          fmaf(-2.f, D[prv][6], c2q[prv][2]),
                          fmaf(-2.f, D[prv][7], c2q[prv][3]), gi);
                }
                // (4) MMAs for this gp (results consumed next iteration)
                #pragma unroll
                for (int q = 0; q < 8; ++q) D[cur][q] = 0.f;
                #pragma unroll
                for (int p = 0; p < 2; ++p) {
                    #pragma unroll
                    for (int j = 0; j < 2; ++j) {
                        int ks = 2 * p + j;
                        mma16816(&D[cur][0], Ah[ks], bf[p*8 + 2*j], bf[p*8 + 2*j + 1]);
                        mma16816(&D[cur][4], Ah[ks], bf[p*8 + 4 + 2*j], bf[p*8 + 4 + 2*j + 1]);
                    }
                }
            }
            __syncthreads();
            buf ^= 1;
        }

        // ---- tail fold for the last gp (global gp 63, parity 1) ----
        {
            uint32_t gi = (uint32_t)(KCB - 16 + (lane & 3) * 2);
            fold4(Ka1, Ka2, Ka3,
                  fmaf(-2.f, D[1][0], c2q[1][0]), fmaf(-2.f, D[1][1], c2q[1][1]),
                  fmaf(-2.f, D[1][4], c2q[1][2]), fmaf(-2.f, D[1][5], c2q[1][3]), gi);
            fold4(Kb1, Kb2, Kb3,
                  fmaf(-2.f, D[1][2], c2q[1][0]), fmaf(-2.f, D[1][3], c2q[1][1]),
                  fmaf(-2.f, D[1][6], c2q[1][2]), fmaf(-2.f, D[1][7], c2q[1][3]), gi);
        }

        // ---- merge across the 4 lanes of each row quad (key space) ----
        lanemerge(Ka1, Ka2, Ka3, 1);
        lanemerge(Ka1, Ka2, Ka3, 2);
        lanemerge(Kb1, Kb2, Kb3, 1);
        lanemerge(Kb1, Kb2, Kb3, 2);
        if ((lane & 3) == 0) {
            int vA = warp * 16 + (lane >> 2), vB = vA + 8;
            float m1a = unkey(Ka1), m2a = unkey(Ka2), m3a = unkey(Ka3);
            float m1b = unkey(Kb1), m2b = unkey(Kb2), m3b = unkey(Kb3);
            sidx[vA] = (int)(Ka1 & 1023u); sidx2[vA] = (int)(Ka2 & 1023u);
            sidx[vB] = (int)(Kb1 & 1023u); sidx2[vB] = (int)(Kb2 & 1023u);
            int fA = (m3a - m1a < MARGIN) ? 2 : ((m2a - m1a < MARGIN) ? 1 : 0);
            int fB = (m3b - m1b < MARGIN) ? 2 : ((m2b - m1b < MARGIN) ? 1 : 0);
            sflg[vA] = fA; sflg[vB] = fB;
            if (fA == 2) { int p = atomicAdd(nlist, 1); list[p] = vA; }
            if (fB == 2) { int p = atomicAdd(nlist, 1); list[p] = vB; }
        }
        __syncthreads();

        // ---- full exact rescans (rare) ----
        int nf = *nlist;
        for (int f = 0; f < nf; ++f) {
            int vr = list[f];
            if (tid == 0) *redk = ~0ull;
            if (v == vr) {
                #pragma unroll
                for (int i = 0; i < 8; ++i)
                    *(float4*)(rstage + h * 32 + 4*i) =
                        make_float4(r[4*i], r[4*i+1], r[4*i+2], r[4*i+3]);
            }
            __syncthreads();
            unsigned long long bk = ~0ull;
            #pragma unroll 1
            for (int c = tid; c < KCB; c += NTHR) {
                const float4* cw = (const float4*)(cb + ((size_t)l * KCB + c) * DIM);
                const float4* rp = (const float4*)rstage;
                float s = 0.f;
                #pragma unroll
                for (int i = 0; i < 16; ++i) {
                    float4 a = rp[i], bq = cw[i];
                    s += a.x*bq.x + a.y*bq.y + a.z*bq.z + a.w*bq.w;
                }
                float dist = fmaf(-2.f, s, g_c2[l * KCB + c]);
                uint32_t fb = __float_as_uint(dist);
                fb ^= (fb & 0x80000000u) ? 0xFFFFFFFFu : 0x80000000u;
                unsigned long long key = ((unsigned long long)fb << 32) | (unsigned)c;
                if (key < bk) bk = key;
            }
            atomicMin(redk, bk);
            __syncthreads();
            if (tid == 0) sidx[vr] = (int)(*redk & 0xffffffffu);
            __syncthreads();
        }

        // ---- exact duels (parallel, per-vector owner pair) ----
        int idx = sidx[v];
        int fl  = sflg[v];
        float sA = 0.f, sB = 0.f;
        int iA = idx, iB = sidx2[v];
        if (fl == 1) {
            const float4* ca = (const float4*)(cb + ((size_t)l * KCB + iA) * DIM + h * 32);
            const float4* cbq = (const float4*)(cb + ((size_t)l * KCB + iB) * DIM + h * 32);
            #pragma unroll
            for (int i = 0; i < 8; ++i) {
                float4 a = ca[i], b = cbq[i];
                sA += r[4*i]*a.x + r[4*i+1]*a.y + r[4*i+2]*a.z + r[4*i+3]*a.w;
                sB += r[4*i]*b.x + r[4*i+1]*b.y + r[4*i+2]*b.z + r[4*i+3]*b.w;
            }
        }
        sA += __shfl_xor_sync(0xffffffffu, sA, 1);
        sB += __shfl_xor_sync(0xffffffffu, sB, 1);
        if (fl == 1) {
            float dA = fmaf(-2.f, sA, g_c2[l * KCB + iA]);
            float dB = fmaf(-2.f, sB, g_c2[l * KCB + iB]);
            idx = lexless(dB, iB, dA, iA) ? iB : iA;
        }

        // ---- commit ----
        {
            const float4* q = (const float4*)(cb + ((size_t)l * KCB + idx) * DIM + h * 32);
            float sse = 0.f;
            #pragma unroll
            for (int i = 0; i < 8; ++i) {
                float4 qv = q[i];
                r[4*i]   -= qv.x; r[4*i+1] -= qv.y;
                r[4*i+2] -= qv.z; r[4*i+3] -= qv.w;
                sse += r[4*i]*r[4*i] + r[4*i+1]*r[4*i+1]
                     + r[4*i+2]*r[4*i+2] + r[4*i+3]*r[4*i+3];
            }
            double ds = (double)sse;
            #pragma unroll
            for (int o = 16; o; o >>= 1) ds += __shfl_down_sync(0xffffffffu, ds, o);
            if (lane == 0) atomicAdd(&g_mse[l], ds);
        }
        if (h == 0) {
            atomicAdd(&g_counts[l * KCB + idx], 1);
            out[QELEMS + (size_t)l * NVEC + n0 + v] = (float)idx;
        }
        __syncthreads();
    }

    // ---- quantized = x - final residual (coalesced via B0/B1 staging) ----
    float* rs = (float*)(smem + SM_B0);
    #pragma unroll
    for (int i = 0; i < 8; ++i)
        *(float4*)(rs + v * 64 + h * 32 + 4*i) =
            make_float4(r[4*i], r[4*i+1], r[4*i+2], r[4*i+3]);
    __syncthreads();
    {
        const float4* xp4 = (const float4*)(x + n0 * DIM);
        const float4* rs4 = (const float4*)rs;
        float4*       op4 = (float4*)(out + n0 * DIM);
        #pragma unroll
        for (int g = tid; g < CTAV * 16; g += NTHR) {
            float4 xv = xp4[g], rv = rs4[g];
            op4[g] = make_float4(xv.x - rv.x, xv.y - rv.y,
                                 xv.z - rv.z, xv.w - rv.w);
        }
    }

    // ---- last CTA runs finalize ----
    int* slast = (int*)(smem + SM_LAST);
    if (tid == 0) {
        __threadfence();
        *slast = (atomicAdd(&g_done, 1) == (int)gridDim.x - 1) ? 1 : 0;
    }
    __syncthreads();
    if (*slast) {
        __threadfence();
        double* ws = (double*)(smem + SM_WS);
        double total = 0.0;
        for (int l = 0; l < LEVELS; ++l) {
            float esum = 0.f;
            for (int i = tid; i < KCB; i += NTHR) {
                float p = (float)g_counts[l * KCB + i] / (float)NVEC;
                esum += -(p * logf(p + 1e-10f));
            }
            double e = (double)esum;
            #pragma unroll
            for (int o = 16; o; o >>= 1) e += __shfl_down_sync(0xffffffffu, e, o);
            if ((tid & 31) == 0) ws[tid >> 5] = e;
            __syncthreads();
            if (tid == 0) {
                double ent = 0.0;
                #pragma unroll
                for (int w = 0; w < 8; ++w) ent += ws[w];
                total += 1.25 * (g_mse[l] / ((double)NVEC * DIM)) + 0.1 * ent;
            }
            __syncthreads();
        }
        if (tid == 0) out[QELEMS + (size_t)LEVELS * NVEC] = (float)total;
    }
}

extern "C" void kernel_launch(void* const* d_in, const int* in_sizes, int n_in,
                              void* d_out, int out_size) {
    const float* x  = (const float*)d_in[0];
    const float* cb = (const float*)d_in[1];
    float* out = (float*)d_out;

    cudaFuncSetAttribute(rvq_mma_kernel,
                         cudaFuncAttributeMaxDynamicSharedMemorySize, SMEM_TOTAL);

    prep_kernel<<<16, 256>>>(cb);
    rvq_mma_kernel<<<NVEC / CTAV, NTHR, SMEM_TOTAL>>>(x, cb, out);
}

// round 11
// speedup vs baseline: 1.1524x; 1.0034x over previous
#include <cuda_runtime.h>
#include <cuda_bf16.h>
#include <math.h>
#include <stdint.h>

#define LEVELS 4
#define KCB    1024
#define DIM    64
#define NVEC   131072
#define CTAV   128
#define NTHR   256
#define CHUNK  128
#define NCHNK  (KCB / CHUNK)          // 8
#define QELEMS ((size_t)NVEC * DIM)
#define MARGIN 0.6f

// ---------------- device scratch ----------------
__device__ double        g_mse[LEVELS];
__device__ int           g_counts[LEVELS * KCB];
__device__ float         g_c2[LEVELS * KCB];
__device__ __nv_bfloat16 g_cbh[LEVELS * KCB * DIM];
__device__ int           g_done;

// ---------------- SMEM layout (bytes); rows are 128B, XOR-swizzled ----------------
#define SM_AH     0            // 128 rows * 128B = 16384
#define SM_B0     16384        // 16384
#define SM_B1     32768        // 16384
#define SM_C2     49152        // 2 bufs * 128 f32 = 1024
#define SM_IDX    50176        // 128 i32
#define SM_IDX2   50688
#define SM_FLG    51200
#define SM_LIST   51712
#define SM_RST    52224        // 64 f32
#define SM_NL     52480
#define SM_REDK   52488
#define SM_LAST   52496
#define SM_WS     52504        // 8 doubles
#define SMEM_TOTAL 52576

// ---------------- helpers ----------------
__device__ __forceinline__ uint32_t smem_u32(const void* p) {
    uint32_t a;
    asm("{ .reg .u64 t; cvta.to.shared.u64 t, %1; cvt.u32.u64 %0, t; }"
        : "=r"(a) : "l"(p));
    return a;
}
__device__ __forceinline__ void ldsm4(uint32_t r[4], uint32_t addr) {
    asm volatile("ldmatrix.sync.aligned.m8n8.x4.shared.b16 {%0,%1,%2,%3}, [%4];"
                 : "=r"(r[0]), "=r"(r[1]), "=r"(r[2]), "=r"(r[3]) : "r"(addr));
}
__device__ __forceinline__ void mma16816(float* d, const uint32_t* a,
                                         uint32_t b0, uint32_t b1) {
    asm volatile(
        "mma.sync.aligned.m16n8k16.row.col.f32.bf16.bf16.f32 "
        "{%0,%1,%2,%3}, {%4,%5,%6,%7}, {%8,%9}, {%0,%1,%2,%3};"
        : "+f"(d[0]), "+f"(d[1]), "+f"(d[2]), "+f"(d[3])
        : "r"(a[0]), "r"(a[1]), "r"(a[2]), "r"(a[3]), "r"(b0), "r"(b1));
}
#define CP16(dst, src) asm volatile("cp.async.cg.shared.global [%0], [%1], 16;" :: "r"(dst), "l"(src))
#define CP_COMMIT()    asm volatile("cp.async.commit_group;" ::: "memory")
#define CP_WAIT0()     asm volatile("cp.async.wait_group 0;" ::: "memory")
#define CP_WAIT1()     asm volatile("cp.async.wait_group 1;" ::: "memory")

// sortable key: monotone f32 map, low 10 bits replaced by codeword index
__device__ __forceinline__ uint32_t dkey(float d, uint32_t idx) {
    uint32_t fb = __float_as_uint(d);
    fb ^= (uint32_t)((int32_t)fb >> 31) | 0x80000000u;
    return (fb & 0xFFFFFC00u) | (idx & 1023u);
}
__device__ __forceinline__ float unkey(uint32_t k) {
    uint32_t u = k & 0xFFFFFC00u;
    uint32_t fb = (u & 0x80000000u) ? (u ^ 0x80000000u) : (~u & 0xFFFFFC00u);
    return __uint_as_float(fb);
}
__device__ __forceinline__ void ins3(uint32_t& K1, uint32_t& K2, uint32_t& K3,
                                     uint32_t g) {
    uint32_t b = umax(K1, g); K1 = umin(K1, g);
    uint32_t d = umax(K2, b); K2 = umin(K2, b);
    K3 = umin(K3, d);
}
__device__ __forceinline__ void ins2(uint32_t& K2, uint32_t& K3, uint32_t g) {
    uint32_t f = umax(K2, g); K2 = umin(K2, g);
    K3 = umin(K3, f);
}
// fold 4 dists into running top-3 keys (true 3-of-4 extraction)
__device__ __forceinline__ void fold4(uint32_t& K1, uint32_t& K2, uint32_t& K3,
                                      float d0, float d1, float d8, float d9,
                                      uint32_t gi) {
    uint32_t k0 = dkey(d0, gi),     k1 = dkey(d1, gi + 1);
    uint32_t k8 = dkey(d8, gi + 8), k9 = dkey(d9, gi + 9);
    uint32_t lo1 = umin(k0, k1), hi1 = umax(k0, k1);
    uint32_t lo2 = umin(k8, k9), hi2 = umax(k8, k9);
    uint32_t g1 = umin(lo1, lo2);
    uint32_t m  = umax(lo1, lo2), n = umin(hi1, hi2);
    uint32_t g2 = umin(m, n);
    uint32_t g3 = umin(umax(m, n), umax(hi1, hi2));
    ins3(K1, K2, K3, g1);
    ins2(K2, K3, g2);
    K3 = umin(K3, g3);
}
__device__ __forceinline__ void lanemerge(uint32_t& K1, uint32_t& K2,
                                          uint32_t& K3, int mx) {
    uint32_t o1 = __shfl_xor_sync(0xffffffffu, K1, mx);
    uint32_t o2 = __shfl_xor_sync(0xffffffffu, K2, mx);
    uint32_t o3 = __shfl_xor_sync(0xffffffffu, K3, mx);
    ins3(K1, K2, K3, o1);
    ins2(K2, K3, o2);
    K3 = umin(K3, o3);
}
__device__ __forceinline__ bool lexless(float v1, int j1, float v2, int j2) {
    return v1 < v2 || (v1 == v2 && j1 < j2);
}

// ---------------- prep kernel ----------------
__global__ void prep_kernel(const float* __restrict__ cb) {
    int t = blockIdx.x * blockDim.x + threadIdx.x;
    if (t == 0) g_done = 0;
    if (t < LEVELS) g_mse[t] = 0.0;
    if (t < LEVELS * KCB) {
        g_counts[t] = 0;
        const float* v = cb + (size_t)t * DIM;
        __nv_bfloat16* dh = g_cbh + (size_t)t * DIM;
        float s = 0.f;
        #pragma unroll
        for (int d = 0; d < DIM; ++d) {
            float f = v[d];
            s += f * f;
            dh[d] = __float2bfloat16(f);
        }
        g_c2[t] = s;
    }
}

// ---------------- main kernel ----------------
__global__ __launch_bounds__(NTHR, 3)
void rvq_mma_kernel(const float* __restrict__ x,
                    const float* __restrict__ cb,
                    float* __restrict__ out) {
    extern __shared__ char smem[];
    const uint32_t sb = smem_u32(smem);
    const int tid  = threadIdx.x;
    const int lane = tid & 31, warp = tid >> 5;
    const int v = tid >> 1, h = tid & 1;
    const size_t n0 = (size_t)blockIdx.x * CTAV;

    int*   sidx  = (int*)(smem + SM_IDX);
    int*   sidx2 = (int*)(smem + SM_IDX2);
    int*   sflg  = (int*)(smem + SM_FLG);
    int*   list  = (int*)(smem + SM_LIST);
    float* rstage = (float*)(smem + SM_RST);
    int*   nlist = (int*)(smem + SM_NL);
    unsigned long long* redk = (unsigned long long*)(smem + SM_REDK);

    float r[32];
    {
        const float4* xp = (const float4*)(x + (n0 + v) * DIM + h * 32);
        #pragma unroll
        for (int i = 0; i < 8; ++i) {
            float4 t4 = xp[i];
            r[4*i] = t4.x; r[4*i+1] = t4.y; r[4*i+2] = t4.z; r[4*i+3] = t4.w;
        }
    }

    for (int l = 0; l < LEVELS; ++l) {
        // ---- stage A (bf16, 128B rows, XOR-swizzled 16B chunks) ----
        #pragma unroll
        for (int i = 0; i < 16; ++i) {
            __nv_bfloat16 h0 = __float2bfloat16(r[2*i]);
            __nv_bfloat16 h1 = __float2bfloat16(r[2*i+1]);
            uint32_t wh = (uint32_t)__bfloat16_as_ushort(h0) |
                          ((uint32_t)__bfloat16_as_ushort(h1) << 16);
            int chunk = (h * 4 + (i >> 2)) ^ (v & 7);
            int off = v * 128 + chunk * 16 + (i & 3) * 4;
            *(uint32_t*)(smem + SM_AH + off) = wh;
        }
        if (tid == 0) *nlist = 0;

        // ---- prefetch B chunk 0 (swizzled stores) ----
        {
            const float4* srh = (const float4*)(g_cbh + (size_t)l * KCB * DIM);
            #pragma unroll
            for (int g = tid; g < CHUNK * 8; g += NTHR) {
                uint32_t dst = (uint32_t)(((g & ~7) + ((g ^ (g >> 3)) & 7)) * 16);
                CP16(sb + SM_B0 + dst, srh + g);
            }
            if (tid < 32)
                CP16(sb + SM_C2 + tid * 16, (const float4*)(g_c2 + l * KCB) + tid);
            CP_COMMIT();
        }
        __syncthreads();

        // ---- A fragments for the level (swizzle-aware) ----
        uint32_t Ah[4][4];
        {
            int r7   = lane >> 2;                 // rowA & 7
            int rowA = warp * 16 + r7;
            int q4   = (lane & 3) * 4;            // byte offset within 16B chunk
            #pragma unroll
            for (int ks = 0; ks < 4; ++ks) {
                int ch0 = (ks * 2)     ^ r7;
                int ch1 = (ks * 2 + 1) ^ r7;
                int o00 = rowA * 128 + ch0 * 16 + q4;
                int o01 = rowA * 128 + ch1 * 16 + q4;
                Ah[ks][0] = *(const uint32_t*)(smem + SM_AH + o00);
                Ah[ks][1] = *(const uint32_t*)(smem + SM_AH + o00 + 1024);
                Ah[ks][2] = *(const uint32_t*)(smem + SM_AH + o01);
                Ah[ks][3] = *(const uint32_t*)(smem + SM_AH + o01 + 1024);
            }
        }

        uint32_t Ka1 = 0xFFFFFFFFu, Ka2 = 0xFFFFFFFFu, Ka3 = 0xFFFFFFFFu;
        uint32_t Kb1 = 0xFFFFFFFFu, Kb2 = 0xFFFFFFFFu, Kb3 = 0xFFFFFFFFu;

        // pipelined D / c2 (parity-double-buffered registers)
        float D[2][8];
        float c2q[2][4];
        #pragma unroll
        for (int q = 0; q < 8; ++q) D[1][q] = -3.4e38f;
        #pragma unroll
        for (int q = 0; q < 4; ++q) c2q[1][q] = 0.f;

        int buf = 0;
        for (int ci = 0; ci < NCHNK; ++ci) {
            if (ci < NCHNK - 1) {
                const float4* srh = (const float4*)
                    (g_cbh + ((size_t)l * KCB + (ci + 1) * CHUNK) * DIM);
                uint32_t bdst = sb + (buf ? SM_B0 : SM_B1);
                #pragma unroll
                for (int g = tid; g < CHUNK * 8; g += NTHR) {
                    uint32_t dst = (uint32_t)(((g & ~7) + ((g ^ (g >> 3)) & 7)) * 16);
                    CP16(bdst + dst, srh + g);
                }
                if (tid < 32)
                    CP16(sb + SM_C2 + (buf ^ 1) * 512 + tid * 16,
                         (const float4*)(g_c2 + l * KCB + (ci + 1) * CHUNK) + tid);
                CP_COMMIT();
                CP_WAIT1();
            } else {
                CP_WAIT0();
            }
            __syncthreads();

            const uint32_t bbase = sb + (buf ? SM_B1 : SM_B0);
            const float* c2s = (const float*)(smem + SM_C2 + buf * 512);
            const int c0 = ci * CHUNK;

            #pragma unroll 2
            for (int gp = 0; gp < 8; ++gp) {
                const int cur = gp & 1, prv = cur ^ 1;
                // (1) all LDSMs for this gp — conflict-free swizzled rows
                uint32_t bf[16];
                {
                    int l7 = lane & 7;
                    uint32_t rowb = (uint32_t)((gp * 16 + l7) * 128);
                    uint32_t sw   = (uint32_t)((((lane >> 3) ^ l7) & 7) * 16);
                    ldsm4(bf,      bbase + rowb + sw);
                    ldsm4(bf + 4,  bbase + rowb + sw + 1024);
                    ldsm4(bf + 8,  bbase + rowb + (sw ^ 64));
                    ldsm4(bf + 12, bbase + rowb + (sw ^ 64) + 1024);
                }
                // (2) c2 for this gp (consumed next iteration)
                int nb = gp * 16 + (lane & 3) * 2;
                float2 a2 = *(const float2*)(c2s + nb);
                float2 b2 = *(const float2*)(c2s + nb + 8);
                c2q[cur][0] = a2.x; c2q[cur][1] = a2.y;
                c2q[cur][2] = b2.x; c2q[cur][3] = b2.y;
                // (3) fold PREVIOUS gp's distances — covers LDSM latency
                {
                    uint32_t gi = (uint32_t)(c0 + gp * 16 - 16 + (lane & 3) * 2);
                    fold4(Ka1, Ka2, Ka3,
                          fmaf(-2.f, D[prv][0], c2q[prv][0]),
                          fmaf(-2.f, D[prv][1], c2q[prv][1]),
                          fmaf(-2.f, D[prv][4], c2q[prv][2]),
                          fmaf(-2.f, D[prv][5], c2q[prv][3]), gi);
                    fold4(Kb1, Kb2, Kb3,
                          fmaf(-2.f, D[prv][2], c2q[prv][0]),
                          fmaf(-2.f, D[prv][3], c2q[prv][1]),
                          fmaf(-2.f, D[prv][6], c2q[prv][2]),
                          fmaf(-2.f, D[prv][7], c2q[prv][3]), gi);
                }
                // (4) MMAs for this gp (results consumed next iteration)
                #pragma unroll
                for (int q = 0; q < 8; ++q) D[cur][q] = 0.f;
                #pragma unroll
                for (int p = 0; p < 2; ++p) {
                    #pragma unroll
                    for (int j = 0; j < 2; ++j) {
                        int ks = 2 * p + j;
                        mma16816(&D[cur][0], Ah[ks], bf[p*8 + 2*j], bf[p*8 + 2*j + 1]);
                        mma16816(&D[cur][4], Ah[ks], bf[p*8 + 4 + 2*j], bf[p*8 + 4 + 2*j + 1]);
                    }
                }
            }
            __syncthreads();
            buf ^= 1;
        }

        // ---- tail fold for the last gp (parity 1) ----
        {
            uint32_t gi = (uint32_t)(KCB - 16 + (lane & 3) * 2);
            fold4(Ka1, Ka2, Ka3,
                  fmaf(-2.f, D[1][0], c2q[1][0]), fmaf(-2.f, D[1][1], c2q[1][1]),
                  fmaf(-2.f, D[1][4], c2q[1][2]), fmaf(-2.f, D[1][5], c2q[1][3]), gi);
            fold4(Kb1, Kb2, Kb3,
                  fmaf(-2.f, D[1][2], c2q[1][0]), fmaf(-2.f, D[1][3], c2q[1][1]),
                  fmaf(-2.f, D[1][6], c2q[1][2]), fmaf(-2.f, D[1][7], c2q[1][3]), gi);
        }

        // ---- merge across the 4 lanes of each row quad (key space) ----
        lanemerge(Ka1, Ka2, Ka3, 1);
        lanemerge(Ka1, Ka2, Ka3, 2);
        lanemerge(Kb1, Kb2, Kb3, 1);
        lanemerge(Kb1, Kb2, Kb3, 2);
        if ((lane & 3) == 0) {
            int vA = warp * 16 + (lane >> 2), vB = vA + 8;
            float m1a = unkey(Ka1), m2a = unkey(Ka2), m3a = unkey(Ka3);
            float m1b = unkey(Kb1), m2b = unkey(Kb2), m3b = unkey(Kb3);
            sidx[vA] = (int)(Ka1 & 1023u); sidx2[vA] = (int)(Ka2 & 1023u);
            sidx[vB] = (int)(Kb1 & 1023u); sidx2[vB] = (int)(Kb2 & 1023u);
            int fA = (m3a - m1a < MARGIN) ? 2 : ((m2a - m1a < MARGIN) ? 1 : 0);
            int fB = (m3b - m1b < MARGIN) ? 2 : ((m2b - m1b < MARGIN) ? 1 : 0);
            sflg[vA] = fA; sflg[vB] = fB;
            if (fA == 2) { int p = atomicAdd(nlist, 1); list[p] = vA; }
            if (fB == 2) { int p = atomicAdd(nlist, 1); list[p] = vB; }
        }
        __syncthreads();

        // ---- full exact rescans (rare) ----
        int nf = *nlist;
        for (int f = 0; f < nf; ++f) {
            int vr = list[f];
            if (tid == 0) *redk = ~0ull;
            if (v == vr) {
                #pragma unroll
                for (int i = 0; i < 8; ++i)
                    *(float4*)(rstage + h * 32 + 4*i) =
                        make_float4(r[4*i], r[4*i+1], r[4*i+2], r[4*i+3]);
            }
            __syncthreads();
            unsigned long long bk = ~0ull;
            #pragma unroll 1
            for (int c = tid; c < KCB; c += NTHR) {
                const float4* cw = (const float4*)(cb + ((size_t)l * KCB + c) * DIM);
                const float4* rp = (const float4*)rstage;
                float s = 0.f;
                #pragma unroll
                for (int i = 0; i < 16; ++i) {
                    float4 a = rp[i], bq = cw[i];
                    s += a.x*bq.x + a.y*bq.y + a.z*bq.z + a.w*bq.w;
                }
                float dist = fmaf(-2.f, s, g_c2[l * KCB + c]);
                uint32_t fb = __float_as_uint(dist);
                fb ^= (fb & 0x80000000u) ? 0xFFFFFFFFu : 0x80000000u;
                unsigned long long key = ((unsigned long long)fb << 32) | (unsigned)c;
                if (key < bk) bk = key;
            }
            atomicMin(redk, bk);
            __syncthreads();
            if (tid == 0) sidx[vr] = (int)(*redk & 0xffffffffu);
            __syncthreads();
        }

        // ---- exact duels (parallel, per-vector owner pair) ----
        int idx = sidx[v];
        int fl  = sflg[v];
        float sA = 0.f, sB = 0.f;
        int iA = idx, iB = sidx2[v];
        if (fl == 1) {
            const float4* ca = (const float4*)(cb + ((size_t)l * KCB + iA) * DIM + h * 32);
            const float4* cbq = (const float4*)(cb + ((size_t)l * KCB + iB) * DIM + h * 32);
            #pragma unroll
            for (int i = 0; i < 8; ++i) {
                float4 a = ca[i], b = cbq[i];
                sA += r[4*i]*a.x + r[4*i+1]*a.y + r[4*i+2]*a.z + r[4*i+3]*a.w;
                sB += r[4*i]*b.x + r[4*i+1]*b.y + r[4*i+2]*b.z + r[4*i+3]*b.w;
            }
        }
        sA += __shfl_xor_sync(0xffffffffu, sA, 1);
        sB += __shfl_xor_sync(0xffffffffu, sB, 1);
        if (fl == 1) {
            float dA = fmaf(-2.f, sA, g_c2[l * KCB + iA]);
            float dB = fmaf(-2.f, sB, g_c2[l * KCB + iB]);
            idx = lexless(dB, iB, dA, iA) ? iB : iA;
        }

        // ---- commit ----
        {
            const float4* q = (const float4*)(cb + ((size_t)l * KCB + idx) * DIM + h * 32);
            float sse = 0.f;
            #pragma unroll
            for (int i = 0; i < 8; ++i) {
                float4 qv = q[i];
                r[4*i]   -= qv.x; r[4*i+1] -= qv.y;
                r[4*i+2] -= qv.z; r[4*i+3] -= qv.w;
                sse += r[4*i]*r[4*i] + r[4*i+1]*r[4*i+1]
                     + r[4*i+2]*r[4*i+2] + r[4*i+3]*r[4*i+3];
            }
            double ds = (double)sse;
            #pragma unroll
            for (int o = 16; o; o >>= 1) ds += __shfl_down_sync(0xffffffffu, ds, o);
            if (lane == 0) atomicAdd(&g_mse[l], ds);
        }
        if (h == 0) {
            atomicAdd(&g_counts[l * KCB + idx], 1);
            out[QELEMS + (size_t)l * NVEC + n0 + v] = (float)idx;
        }
        __syncthreads();
    }

    // ---- quantized = x - final residual (coalesced via B0+B1 staging) ----
    float* rs = (float*)(smem + SM_B0);     // 32KB spans B0+B1 (both free now)
    #pragma unroll
    for (int i = 0; i < 8; ++i)
        *(float4*)(rs + v * 64 + h * 32 + 4*i) =
            make_float4(r[4*i], r[4*i+1], r[4*i+2], r[4*i+3]);
    __syncthreads();
    {
        const float4* xp4 = (const float4*)(x + n0 * DIM);
        const float4* rs4 = (const float4*)rs;
        float4*       op4 = (float4*)(out + n0 * DIM);
        #pragma unroll
        for (int g = tid; g < CTAV * 16; g += NTHR) {
            float4 xv = xp4[g], rv = rs4[g];
            op4[g] = make_float4(xv.x - rv.x, xv.y - rv.y,
                                 xv.z - rv.z, xv.w - rv.w);
        }
    }

    // ---- last CTA runs finalize ----
    int* slast = (int*)(smem + SM_LAST);
    if (tid == 0) {
        __threadfence();
        *slast = (atomicAdd(&g_done, 1) == (int)gridDim.x - 1) ? 1 : 0;
    }
    __syncthreads();
    if (*slast) {
        __threadfence();
        double* ws = (double*)(smem + SM_WS);
        double total = 0.0;
        for (int l = 0; l < LEVELS; ++l) {
            float esum = 0.f;
            for (int i = tid; i < KCB; i += NTHR) {
                float p = (float)g_counts[l * KCB + i] / (float)NVEC;
                esum += -(p * logf(p + 1e-10f));
            }
            double e = (double)esum;
            #pragma unroll
            for (int o = 16; o; o >>= 1) e += __shfl_down_sync(0xffffffffu, e, o);
            if ((tid & 31) == 0) ws[tid >> 5] = e;
            __syncthreads();
            if (tid == 0) {
                double ent = 0.0;
                #pragma unroll
                for (int w = 0; w < 8; ++w) ent += ws[w];
                total += 1.25 * (g_mse[l] / ((double)NVEC * DIM)) + 0.1 * ent;
            }
            __syncthreads();
        }
        if (tid == 0) out[QELEMS + (size_t)LEVELS * NVEC] = (float)total;
    }
}

extern "C" void kernel_launch(void* const* d_in, const int* in_sizes, int n_in,
                              void* d_out, int out_size) {
    const float* x  = (const float*)d_in[0];
    const float* cb = (const float*)d_in[1];
    float* out = (float*)d_out;

    cudaFuncSetAttribute(rvq_mma_kernel,
                         cudaFuncAttributeMaxDynamicSharedMemorySize, SMEM_TOTAL);

    prep_kernel<<<16, 256>>>(cb);
    rvq_mma_kernel<<<NVEC / CTAV, NTHR, SMEM_TOTAL>>>(x, cb, out);
}

// round 13
// speedup vs baseline: 1.2664x; 1.0990x over previous
#include <cuda_runtime.h>
#include <cuda_bf16.h>
#include <math.h>
#include <stdint.h>

#define LEVELS 4
#define KCB    1024
#define DIM    64
#define NVEC   131072
#define CTAV   128
#define NTHR   256
#define CHUNK  128
#define NCHNK  (KCB / CHUNK)          // 8
#define QELEMS ((size_t)NVEC * DIM)
#define MARGIN 0.6f
#define BIAS   1024.0f   // makes dist' = c2+BIAS-2dot provably positive:
                         // needs ||r||*||c|| <= BIAS/2 = 512 (norms ~11 in data)

// ---------------- device scratch ----------------
__device__ double        g_mse[LEVELS];
__device__ int           g_counts[LEVELS * KCB];
__device__ float         g_c2[LEVELS * KCB];    // exact ||c||^2 (duel/rescan)
__device__ float         g_c2b[LEVELS * KCB];   // ||c||^2 + BIAS (key path)
__device__ __nv_bfloat16 g_cbh[LEVELS * KCB * DIM];
__device__ int           g_done;

// ---------------- SMEM layout (bytes); rows are 128B, XOR-swizzled ----------------
#define SM_AH     0            // 128 rows * 128B = 16384
#define SM_B0     16384        // 16384
#define SM_B1     32768        // 16384
#define SM_C2     49152        // 2 bufs * 128 f32 = 1024
#define SM_IDX    50176        // 128 i32
#define SM_IDX2   50688
#define SM_FLG    51200
#define SM_LIST   51712
#define SM_RST    52224        // 64 f32
#define SM_NL     52480
#define SM_REDK   52488
#define SM_LAST   52496
#define SM_WS     52504        // 8 doubles
#define SMEM_TOTAL 52576

// ---------------- helpers ----------------
__device__ __forceinline__ uint32_t smem_u32(const void* p) {
    uint32_t a;
    asm("{ .reg .u64 t; cvta.to.shared.u64 t, %1; cvt.u32.u64 %0, t; }"
        : "=r"(a) : "l"(p));
    return a;
}
__device__ __forceinline__ void ldsm4(uint32_t r[4], uint32_t addr) {
    asm volatile("ldmatrix.sync.aligned.m8n8.x4.shared.b16 {%0,%1,%2,%3}, [%4];"
                 : "=r"(r[0]), "=r"(r[1]), "=r"(r[2]), "=r"(r[3]) : "r"(addr));
}
__device__ __forceinline__ void mma16816(float* d, const uint32_t* a,
                                         uint32_t b0, uint32_t b1) {
    asm volatile(
        "mma.sync.aligned.m16n8k16.row.col.f32.bf16.bf16.f32 "
        "{%0,%1,%2,%3}, {%4,%5,%6,%7}, {%8,%9}, {%0,%1,%2,%3};"
        : "+f"(d[0]), "+f"(d[1]), "+f"(d[2]), "+f"(d[3])
        : "r"(a[0]), "r"(a[1]), "r"(a[2]), "r"(a[3]), "r"(b0), "r"(b1));
}
// zero-C form: D = A*B
__device__ __forceinline__ void mma16816z(float* d, const uint32_t* a,
                                          uint32_t b0, uint32_t b1) {
    asm volatile(
        "mma.sync.aligned.m16n8k16.row.col.f32.bf16.bf16.f32 "
        "{%0,%1,%2,%3}, {%4,%5,%6,%7}, {%8,%9}, {%10,%10,%10,%10};"
        : "=f"(d[0]), "=f"(d[1]), "=f"(d[2]), "=f"(d[3])
        : "r"(a[0]), "r"(a[1]), "r"(a[2]), "r"(a[3]), "r"(b0), "r"(b1),
          "f"(0.f));
}
#define CP16(dst, src) asm volatile("cp.async.cg.shared.global [%0], [%1], 16;" :: "r"(dst), "l"(src))
#define CP_COMMIT()    asm volatile("cp.async.commit_group;" ::: "memory")
#define CP_WAIT0()     asm volatile("cp.async.wait_group 0;" ::: "memory")
#define CP_WAIT1()     asm volatile("cp.async.wait_group 1;" ::: "memory")

// keys: dist' = c2+BIAS - 2*dot is strictly positive, so raw IEEE bits are
// monotone. low 10 mantissa bits replaced by codeword index (single LOP3).
__device__ __forceinline__ uint32_t dkey(float d, uint32_t idx) {
    return (__float_as_uint(d) & 0xFFFFFC00u) | idx;
}
__device__ __forceinline__ float unkey(uint32_t k) {
    return __uint_as_float(k & 0xFFFFFC00u);   // biased by +BIAS; gaps cancel
}
__device__ __forceinline__ void ins3(uint32_t& K1, uint32_t& K2, uint32_t& K3,
                                     uint32_t g) {
    uint32_t b = umax(K1, g); K1 = umin(K1, g);
    uint32_t d = umax(K2, b); K2 = umin(K2, b);
    K3 = umin(K3, d);
}
__device__ __forceinline__ void ins2(uint32_t& K2, uint32_t& K3, uint32_t g) {
    uint32_t f = umax(K2, g); K2 = umin(K2, g);
    K3 = umin(K3, f);
}
// fold 4 dists into running top-3 keys (true 3-of-4 extraction)
__device__ __forceinline__ void fold4(uint32_t& K1, uint32_t& K2, uint32_t& K3,
                                      float d0, float d1, float d8, float d9,
                                      uint32_t gi) {
    uint32_t k0 = dkey(d0, gi),     k1 = dkey(d1, gi + 1);
    uint32_t k8 = dkey(d8, gi + 8), k9 = dkey(d9, gi + 9);
    uint32_t lo1 = umin(k0, k1), hi1 = umax(k0, k1);
    uint32_t lo2 = umin(k8, k9), hi2 = umax(k8, k9);
    uint32_t g1 = umin(lo1, lo2);
    uint32_t m  = umax(lo1, lo2), n = umin(hi1, hi2);
    uint32_t g2 = umin(m, n);
    uint32_t g3 = umin(umax(m, n), umax(hi1, hi2));
    ins3(K1, K2, K3, g1);
    ins2(K2, K3, g2);
    K3 = umin(K3, g3);
}
__device__ __forceinline__ void lanemerge(uint32_t& K1, uint32_t& K2,
                                          uint32_t& K3, int mx) {
    uint32_t o1 = __shfl_xor_sync(0xffffffffu, K1, mx);
    uint32_t o2 = __shfl_xor_sync(0xffffffffu, K2, mx);
    uint32_t o3 = __shfl_xor_sync(0xffffffffu, K3, mx);
    ins3(K1, K2, K3, o1);
    ins2(K2, K3, o2);
    K3 = umin(K3, o3);
}
__device__ __forceinline__ bool lexless(float v1, int j1, float v2, int j2) {
    return v1 < v2 || (v1 == v2 && j1 < j2);
}

// ---------------- prep kernel ----------------
__global__ void prep_kernel(const float* __restrict__ cb) {
    int t = blockIdx.x * blockDim.x + threadIdx.x;
    if (t == 0) g_done = 0;
    if (t < LEVELS) g_mse[t] = 0.0;
    if (t < LEVELS * KCB) {
        g_counts[t] = 0;
        const float* v = cb + (size_t)t * DIM;
        __nv_bfloat16* dh = g_cbh + (size_t)t * DIM;
        float s = 0.f;
        #pragma unroll
        for (int d = 0; d < DIM; ++d) {
            float f = v[d];
            s += f * f;
            dh[d] = __float2bfloat16(f);
        }
        g_c2[t]  = s;
        g_c2b[t] = s + BIAS;
    }
}

// ---------------- main kernel ----------------
__global__ __launch_bounds__(NTHR, 3)
void rvq_mma_kernel(const float* __restrict__ x,
                    const float* __restrict__ cb,
                    float* __restrict__ out) {
    extern __shared__ char smem[];
    const uint32_t sb = smem_u32(smem);
    const int tid  = threadIdx.x;
    const int lane = tid & 31, warp = tid >> 5;
    const int v = tid >> 1, h = tid & 1;
    const size_t n0 = (size_t)blockIdx.x * CTAV;

    int*   sidx  = (int*)(smem + SM_IDX);
    int*   sidx2 = (int*)(smem + SM_IDX2);
    int*   sflg  = (int*)(smem + SM_FLG);
    int*   list  = (int*)(smem + SM_LIST);
    float* rstage = (float*)(smem + SM_RST);
    int*   nlist = (int*)(smem + SM_NL);
    unsigned long long* redk = (unsigned long long*)(smem + SM_REDK);

    float r[32];
    {
        const float4* xp = (const float4*)(x + (n0 + v) * DIM + h * 32);
        #pragma unroll
        for (int i = 0; i < 8; ++i) {
            float4 t4 = xp[i];
            r[4*i] = t4.x; r[4*i+1] = t4.y; r[4*i+2] = t4.z; r[4*i+3] = t4.w;
        }
    }

    for (int l = 0; l < LEVELS; ++l) {
        // ---- stage A (bf16, 128B rows, XOR-swizzled 16B chunks) ----
        #pragma unroll
        for (int i = 0; i < 16; ++i) {
            __nv_bfloat16 h0 = __float2bfloat16(r[2*i]);
            __nv_bfloat16 h1 = __float2bfloat16(r[2*i+1]);
            uint32_t wh = (uint32_t)__bfloat16_as_ushort(h0) |
                          ((uint32_t)__bfloat16_as_ushort(h1) << 16);
            int chunk = (h * 4 + (i >> 2)) ^ (v & 7);
            int off = v * 128 + chunk * 16 + (i & 3) * 4;
            *(uint32_t*)(smem + SM_AH + off) = wh;
        }
        if (tid == 0) *nlist = 0;

        // ---- prefetch B chunk 0 (swizzled stores) ----
        {
            const float4* srh = (const float4*)(g_cbh + (size_t)l * KCB * DIM);
            #pragma unroll
            for (int g = tid; g < CHUNK * 8; g += NTHR) {
                uint32_t dst = (uint32_t)(((g & ~7) + ((g ^ (g >> 3)) & 7)) * 16);
                CP16(sb + SM_B0 + dst, srh + g);
            }
            if (tid < 32)
                CP16(sb + SM_C2 + tid * 16, (const float4*)(g_c2b + l * KCB) + tid);
            CP_COMMIT();
        }
        __syncthreads();

        // ---- A fragments for the level (swizzle-aware) ----
        uint32_t Ah[4][4];
        {
            int r7   = lane >> 2;
            int rowA = warp * 16 + r7;
            int q4   = (lane & 3) * 4;
            #pragma unroll
            for (int ks = 0; ks < 4; ++ks) {
                int ch0 = (ks * 2)     ^ r7;
                int ch1 = (ks * 2 + 1) ^ r7;
                int o00 = rowA * 128 + ch0 * 16 + q4;
                int o01 = rowA * 128 + ch1 * 16 + q4;
                Ah[ks][0] = *(const uint32_t*)(smem + SM_AH + o00);
                Ah[ks][1] = *(const uint32_t*)(smem + SM_AH + o00 + 1024);
                Ah[ks][2] = *(const uint32_t*)(smem + SM_AH + o01);
                Ah[ks][3] = *(const uint32_t*)(smem + SM_AH + o01 + 1024);
            }
        }

        uint32_t Ka1 = 0xFFFFFFFFu, Ka2 = 0xFFFFFFFFu, Ka3 = 0xFFFFFFFFu;
        uint32_t Kb1 = 0xFFFFFFFFu, Kb2 = 0xFFFFFFFFu, Kb3 = 0xFFFFFFFFu;

        float D[2][8];
        float c2q[2][4];
        #pragma unroll
        for (int q = 0; q < 8; ++q) D[1][q] = -3.4e38f;   // fake prev: dist=+huge
        #pragma unroll
        for (int q = 0; q < 4; ++q) c2q[1][q] = 0.f;

        int buf = 0;
        for (int ci = 0; ci < NCHNK; ++ci) {
            if (ci < NCHNK - 1) {
                const float4* srh = (const float4*)
                    (g_cbh + ((size_t)l * KCB + (ci + 1) * CHUNK) * DIM);
                uint32_t bdst = sb + (buf ? SM_B0 : SM_B1);
                #pragma unroll
                for (int g = tid; g < CHUNK * 8; g += NTHR) {
                    uint32_t dst = (uint32_t)(((g & ~7) + ((g ^ (g >> 3)) & 7)) * 16);
                    CP16(bdst + dst, srh + g);
                }
                if (tid < 32)
                    CP16(sb + SM_C2 + (buf ^ 1) * 512 + tid * 16,
                         (const float4*)(g_c2b + l * KCB + (ci + 1) * CHUNK) + tid);
                CP_COMMIT();
                CP_WAIT1();
            } else {
                CP_WAIT0();
            }
            __syncthreads();

            const uint32_t bbase = sb + (buf ? SM_B1 : SM_B0);
            const float* c2s = (const float*)(smem + SM_C2 + buf * 512);
            const int c0 = ci * CHUNK;

            #pragma unroll 2
            for (int gp = 0; gp < 8; ++gp) {
                const int cur = gp & 1, prv = cur ^ 1;
                // (1) all LDSMs for this gp
                uint32_t bf[16];
                {
                    int l7 = lane & 7;
                    uint32_t rowb = (uint32_t)((gp * 16 + l7) * 128);
                    uint32_t sw   = (uint32_t)((((lane >> 3) ^ l7) & 7) * 16);
                    ldsm4(bf,      bbase + rowb + sw);
                    ldsm4(bf + 4,  bbase + rowb + sw + 1024);
                    ldsm4(bf + 8,  bbase + rowb + (sw ^ 64));
                    ldsm4(bf + 12, bbase + rowb + (sw ^ 64) + 1024);
                }
                // (2) biased c2 for this gp (consumed next iteration)
                int nb = gp * 16 + (lane & 3) * 2;
                float2 a2 = *(const float2*)(c2s + nb);
                float2 b2 = *(const float2*)(c2s + nb + 8);
                c2q[cur][0] = a2.x; c2q[cur][1] = a2.y;
                c2q[cur][2] = b2.x; c2q[cur][3] = b2.y;
                // (3) fold PREVIOUS gp's distances — covers LDSM latency
                {
                    uint32_t gi = (uint32_t)(c0 + gp * 16 - 16 + (lane & 3) * 2);
                    fold4(Ka1, Ka2, Ka3,
                          fmaf(-2.f, D[prv][0], c2q[prv][0]),
                          fmaf(-2.f, D[prv][1], c2q[prv][1]),
                          fmaf(-2.f, D[prv][4], c2q[prv][2]),
                          fmaf(-2.f, D[prv][5], c2q[prv][3]), gi);
                    fold4(Kb1, Kb2, Kb3,
                          fmaf(-2.f, D[prv][2], c2q[prv][0]),
                          fmaf(-2.f, D[prv][3], c2q[prv][1]),
                          fmaf(-2.f, D[prv][6], c2q[prv][2]),
                          fmaf(-2.f, D[prv][7], c2q[prv][3]), gi);
                }
                // (4) MMAs for this gp — two 2-deep chains per half + FADD merge
                {
                    float T[4];
                    mma16816z(&D[cur][0], Ah[0], bf[0], bf[1]);
                    mma16816 (&D[cur][0], Ah[1], bf[2], bf[3]);
                    mma16816z(T,          Ah[2], bf[8], bf[9]);
                    mma16816 (T,          Ah[3], bf[10], bf[11]);
                    #pragma unroll
                    for (int q = 0; q < 4; ++q) D[cur][q] += T[q];
                    mma16816z(&D[cur][4], Ah[0], bf[4], bf[5]);
                    mma16816 (&D[cur][4], Ah[1], bf[6], bf[7]);
                    mma16816z(T,          Ah[2], bf[12], bf[13]);
                    mma16816 (T,          Ah[3], bf[14], bf[15]);
                    #pragma unroll
                    for (int q = 0; q < 4; ++q) D[cur][4 + q] += T[q];
                }
            }
            __syncthreads();
            buf ^= 1;
        }

        // ---- tail fold for the last gp (parity 1) ----
        {
            uint32_t gi = (uint32_t)(KCB - 16 + (lane & 3) * 2);
            fold4(Ka1, Ka2, Ka3,
                  fmaf(-2.f, D[1][0], c2q[1][0]), fmaf(-2.f, D[1][1], c2q[1][1]),
                  fmaf(-2.f, D[1][4], c2q[1][2]), fmaf(-2.f, D[1][5], c2q[1][3]), gi);
            fold4(Kb1, Kb2, Kb3,
                  fmaf(-2.f, D[1][2], c2q[1][0]), fmaf(-2.f, D[1][3], c2q[1][1]),
                  fmaf(-2.f, D[1][6], c2q[1][2]), fmaf(-2.f, D[1][7], c2q[1][3]), gi);
        }

        // ---- merge across the 4 lanes of each row quad (key space) ----
        lanemerge(Ka1, Ka2, Ka3, 1);
        lanemerge(Ka1, Ka2, Ka3, 2);
        lanemerge(Kb1, Kb2, Kb3, 1);
        lanemerge(Kb1, Kb2, Kb3, 2);
        if ((lane & 3) == 0) {
            int vA = warp * 16 + (lane >> 2), vB = vA + 8;
            float m1a = unkey(Ka1), m2a = unkey(Ka2), m3a = unkey(Ka3);
            float m1b = unkey(Kb1), m2b = unkey(Kb2), m3b = unkey(Kb3);
            sidx[vA] = (int)(Ka1 & 1023u); sidx2[vA] = (int)(Ka2 & 1023u);
            sidx[vB] = (int)(Kb1 & 1023u); sidx2[vB] = (int)(Kb2 & 1023u);
            int fA = (m3a - m1a < MARGIN) ? 2 : ((m2a - m1a < MARGIN) ? 1 : 0);
            int fB = (m3b - m1b < MARGIN) ? 2 : ((m2b - m1b < MARGIN) ? 1 : 0);
            sflg[vA] = fA; sflg[vB] = fB;
            if (fA == 2) { int p = atomicAdd(nlist, 1); list[p] = vA; }
            if (fB == 2) { int p = atomicAdd(nlist, 1); list[p] = vB; }
        }
        __syncthreads();

        // ---- full exact rescans (rare) ----
        int nf = *nlist;
        for (int f = 0; f < nf; ++f) {
            int vr = list[f];
            if (tid == 0) *redk = ~0ull;
            if (v == vr) {
                #pragma unroll
                for (int i = 0; i < 8; ++i)
                    *(float4*)(rstage + h * 32 + 4*i) =
                        make_float4(r[4*i], r[4*i+1], r[4*i+2], r[4*i+3]);
            }
            __syncthreads();
            unsigned long long bk = ~0ull;
            #pragma unroll 1
            for (int c = tid; c < KCB; c += NTHR) {
                const float4* cw = (const float4*)(cb + ((size_t)l * KCB + c) * DIM);
                const float4* rp = (const float4*)rstage;
                float s = 0.f;
                #pragma unroll
                for (int i = 0; i < 16; ++i) {
                    float4 a = rp[i], bq = cw[i];
                    s += a.x*bq.x + a.y*bq.y + a.z*bq.z + a.w*bq.w;
                }
                float dist = fmaf(-2.f, s, g_c2[l * KCB + c]);
                uint32_t fb = __float_as_uint(dist);
                fb ^= (fb & 0x80000000u) ? 0xFFFFFFFFu : 0x80000000u;
                unsigned long long key = ((unsigned long long)fb << 32) | (unsigned)c;
                if (key < bk) bk = key;
            }
            atomicMin(redk, bk);
            __syncthreads();
            if (tid == 0) sidx[vr] = (int)(*redk & 0xffffffffu);
            __syncthreads();
        }

        // ---- exact duels (parallel, per-vector owner pair) ----
        int idx = sidx[v];
        int fl  = sflg[v];
        float sA = 0.f, sB = 0.f;
        int iA = idx, iB = sidx2[v];
        if (fl == 1) {
            const float4* ca = (const float4*)(cb + ((size_t)l * KCB + iA) * DIM + h * 32);
            const float4* cbq = (const float4*)(cb + ((size_t)l * KCB + iB) * DIM + h * 32);
            #pragma unroll
            for (int i = 0; i < 8; ++i) {
                float4 a = ca[i], b = cbq[i];
                sA += r[4*i]*a.x + r[4*i+1]*a.y + r[4*i+2]*a.z + r[4*i+3]*a.w;
                sB += r[4*i]*b.x + r[4*i+1]*b.y + r[4*i+2]*b.z + r[4*i+3]*b.w;
            }
        }
        sA += __shfl_xor_sync(0xffffffffu, sA, 1);
        sB += __shfl_xor_sync(0xffffffffu, sB, 1);
        if (fl == 1) {
            float dA = fmaf(-2.f, sA, g_c2[l * KCB + iA]);
            float dB = fmaf(-2.f, sB, g_c2[l * KCB + iB]);
            idx = lexless(dB, iB, dA, iA) ? iB : iA;
        }

        // ---- commit ----
        {
            const float4* q = (const float4*)(cb + ((size_t)l * KCB + idx) * DIM + h * 32);
            float sse = 0.f;
            #pragma unroll
            for (int i = 0; i < 8; ++i) {
                float4 qv = q[i];
                r[4*i]   -= qv.x; r[4*i+1] -= qv.y;
                r[4*i+2] -= qv.z; r[4*i+3] -= qv.w;
                sse += r[4*i]*r[4*i] + r[4*i+1]*r[4*i+1]
                     + r[4*i+2]*r[4*i+2] + r[4*i+3]*r[4*i+3];
            }
            double ds = (double)sse;
            #pragma unroll
            for (int o = 16; o; o >>= 1) ds += __shfl_down_sync(0xffffffffu, ds, o);
            if (lane == 0) atomicAdd(&g_mse[l], ds);
        }
        if (h == 0) {
            atomicAdd(&g_counts[l * KCB + idx], 1);
            out[QELEMS + (size_t)l * NVEC + n0 + v] = (float)idx;
        }
        __syncthreads();
    }

    // ---- quantized = x - final residual (coalesced via B0+B1 staging) ----
    float* rs = (float*)(smem + SM_B0);
    #pragma unroll
    for (int i = 0; i < 8; ++i)
        *(float4*)(rs + v * 64 + h * 32 + 4*i) =
            make_float4(r[4*i], r[4*i+1], r[4*i+2], r[4*i+3]);
    __syncthreads();
    {
        const float4* xp4 = (const float4*)(x + n0 * DIM);
        const float4* rs4 = (const float4*)rs;
        float4*       op4 = (float4*)(out + n0 * DIM);
        #pragma unroll
        for (int g = tid; g < CTAV * 16; g += NTHR) {
            float4 xv = xp4[g], rv = rs4[g];
            op4[g] = make_float4(xv.x - rv.x, xv.y - rv.y,
                                 xv.z - rv.z, xv.w - rv.w);
        }
    }

    // ---- last CTA runs finalize ----
    int* slast = (int*)(smem + SM_LAST);
    if (tid == 0) {
        __threadfence();
        *slast = (atomicAdd(&g_done, 1) == (int)gridDim.x - 1) ? 1 : 0;
    }
    __syncthreads();
    if (*slast) {
        __threadfence();
        double* ws = (double*)(smem + SM_WS);
        double total = 0.0;
        for (int l = 0; l < LEVELS; ++l) {
            float esum = 0.f;
            for (int i = tid; i < KCB; i += NTHR) {
                float p = (float)g_counts[l * KCB + i] / (float)NVEC;
                esum += -(p * logf(p + 1e-10f));
            }
            double e = (double)esum;
            #pragma unroll
            for (int o = 16; o; o >>= 1) e += __shfl_down_sync(0xffffffffu, e, o);
            if ((tid & 31) == 0) ws[tid >> 5] = e;
            __syncthreads();
            if (tid == 0) {
                double ent = 0.0;
                #pragma unroll
                for (int w = 0; w < 8; ++w) ent += ws[w];
                total += 1.25 * (g_mse[l] / ((double)NVEC * DIM)) + 0.1 * ent;
            }
            __syncthreads();
        }
        if (tid == 0) out[QELEMS + (size_t)LEVELS * NVEC] = (float)total;
    }
}

extern "C" void kernel_launch(void* const* d_in, const int* in_sizes, int n_in,
                              void* d_out, int out_size) {
    const float* x  = (const float*)d_in[0];
    const float* cb = (const float*)d_in[1];
    float* out = (float*)d_out;

    cudaFuncSetAttribute(rvq_mma_kernel,
                         cudaFuncAttributeMaxDynamicSharedMemorySize, SMEM_TOTAL);

    prep_kernel<<<16, 256>>>(cb);
    rvq_mma_kernel<<<NVEC / CTAV, NTHR, SMEM_TOTAL>>>(x, cb, out);
}